// round 5
// baseline (speedup 1.0000x reference)
#include <cuda_runtime.h>
#include <math.h>

#define BB 4
#define NN 1024
#define CC 768
#define HH 12
#define HD 64
#define QKV3 (3*CC)          // 2304
#define MROWS (2*BB*NN)      // 8192
#define PERSB (HH*NN*HD)     // 786432 floats per (stream,b)

// -------- scratch (device globals; no allocation) --------
__device__ float g_q  [2*BB*HH*NN*HD];   // [s][b][h][n][d]  (tf32-rounded)
__device__ float g_k  [2*BB*HH*NN*HD];
__device__ float g_v  [2*BB*HH*NN*HD];
__device__ float g_ctx[2*BB*HH*NN*HD];   // [p][b][h][n][d]  (tf32-rounded)
__device__ float g_x  [MROWS*CC];        // rounded [before;after]
__device__ float g_wq [QKV3*CC];         // rounded W_qkv
__device__ float g_wp [CC*CC];           // rounded W_proj

// -------- helpers --------
__device__ __forceinline__ unsigned f2t(float x) {
    unsigned u; asm("cvt.rna.tf32.f32 %0, %1;" : "=r"(u) : "f"(x)); return u;
}
__device__ __forceinline__ float f2tf(float x) {
    return __uint_as_float(f2t(x));
}
__device__ __forceinline__ void mma8(float* c, const unsigned* a, const unsigned* b) {
    asm volatile("mma.sync.aligned.m16n8k8.row.col.f32.tf32.tf32.f32 "
        "{%0,%1,%2,%3}, {%4,%5,%6,%7}, {%8,%9}, {%0,%1,%2,%3};"
        : "+f"(c[0]), "+f"(c[1]), "+f"(c[2]), "+f"(c[3])
        : "r"(a[0]), "r"(a[1]), "r"(a[2]), "r"(a[3]), "r"(b[0]), "r"(b[1]));
}
__device__ __forceinline__ void ldsm4(unsigned& r0, unsigned& r1, unsigned& r2,
                                      unsigned& r3, unsigned addr) {
    asm volatile("ldmatrix.sync.aligned.m8n8.x4.shared.b16 {%0,%1,%2,%3}, [%4];"
        : "=r"(r0), "=r"(r1), "=r"(r2), "=r"(r3) : "r"(addr));
}
__device__ __forceinline__ unsigned s2u(const void* p) {
    return (unsigned)__cvta_generic_to_shared(p);
}
__device__ __forceinline__ void cp16(unsigned dst, const float* src) {
    asm volatile("cp.async.cg.shared.global [%0], [%1], 16;" :: "r"(dst), "l"(src));
}
#define CPCOMMIT() asm volatile("cp.async.commit_group;")

// GEMM tiling constants (qkv & proj): 128x128 block, K-step 32, 8 warps (2x4)
#define KST 36               // smem row stride (words): 9x16B units, LDSM conflict-free
#define ABUFW (128*KST)      // 4608 words per A tile
#define BUFW  (2*ABUFW)      // 9216 words per stage (A + B)
#define CST 133              // epilogue C stride

// per-thread ldmatrix byte offsets (within a tile, stride KST)
#define AOFF_G(lane) ((((lane)&15)*KST + ((lane)>>4)*4)*4)
#define BOFF_G(lane) (((((((lane)>>4)<<3)) + ((lane)&7))*KST + (((lane)>>3)&1)*4)*4)

// =====================================================================
// Kernel 0: pre-round inputs to tf32 (once). One float4 per thread.
// =====================================================================
#define XQ4 (MROWS*CC/4)     // 1572864
#define WQ4 (QKV3*CC/4)      // 442368
#define PQ4 (CC*CC/4)        // 147456
#define PRTOT (XQ4+WQ4+PQ4)  // 2162688  (exactly 8448*256)

__global__ __launch_bounds__(256) void preround_kernel(
    const float* __restrict__ before, const float* __restrict__ after,
    const float* __restrict__ Wqkv, const float* __restrict__ Wp)
{
    int i = blockIdx.x*256 + threadIdx.x;
    float4 v; float* dst;
    if (i < XQ4) {
        v = (i < XQ4/2) ? ((const float4*)before)[i]
                        : ((const float4*)after)[i - XQ4/2];
        dst = g_x + (size_t)i*4;
    } else if (i < XQ4 + WQ4) {
        v = ((const float4*)Wqkv)[i - XQ4];
        dst = g_wq + (size_t)(i - XQ4)*4;
    } else {
        v = ((const float4*)Wp)[i - XQ4 - WQ4];
        dst = g_wp + (size_t)(i - XQ4 - WQ4)*4;
    }
    float4 o;
    o.x = f2tf(v.x); o.y = f2tf(v.y); o.z = f2tf(v.z); o.w = f2tf(v.w);
    *(float4*)dst = o;
}

// =====================================================================
// Kernel 1: QKV GEMM (tf32 mma + ldmatrix + cp.async db, NO cvt) + LN.
// =====================================================================
__global__ __launch_bounds__(256) void qkv_gemm_mma(
    const float* __restrict__ ln_g, const float* __restrict__ ln_b)
{
    extern __shared__ __align__(16) unsigned sq[];   // 2*BUFW words
    __shared__ float s_lng[64], s_lnb[64];
    const int tid = threadIdx.x;
    if (tid < 64) { s_lng[tid] = ln_g[tid]; s_lnb[tid] = ln_b[tid]; }

    const int warp = tid >> 5, lane = tid & 31;
    const int wm = warp >> 2, wn = warp & 3;
    const int g = lane >> 2, t = lane & 3;
    const int mt = blockIdx.y;
    const int bn = blockIdx.x * 128;
    const unsigned smb = s2u(sq);

    const float* asrc[4]; unsigned adst[4];
    const float* bsrc[4]; unsigned bdst[4];
    #pragma unroll
    for (int i = 0; i < 4; i++) {
        int c = tid + i*256, row = c >> 3, u4 = (c & 7) * 4;
        asrc[i] = g_x + (size_t)(mt*128 + row)*CC + u4;
        adst[i] = smb + (row*KST + u4)*4;
        bsrc[i] = g_wq + (size_t)(bn + row)*CC + u4;
        bdst[i] = smb + (ABUFW + row*KST + u4)*4;
    }
    const unsigned aoff = AOFF_G(lane);
    const unsigned boff = BOFF_G(lane);

    float acc[4][4][4] = {};

    #pragma unroll
    for (int i = 0; i < 4; i++) { cp16(adst[i], asrc[i]); cp16(bdst[i], bsrc[i]); }
    CPCOMMIT();

    for (int kt = 0; kt < 24; kt++) {
        if (kt < 23) {
            unsigned bo = ((kt+1) & 1) * BUFW * 4;
            #pragma unroll
            for (int i = 0; i < 4; i++) {
                cp16(adst[i] + bo, asrc[i] + (kt+1)*32);
                cp16(bdst[i] + bo, bsrc[i] + (kt+1)*32);
            }
            CPCOMMIT();
            asm volatile("cp.async.wait_group 1;");
        } else {
            asm volatile("cp.async.wait_group 0;");
        }
        __syncthreads();
        const unsigned Ab = smb + (kt & 1) * BUFW * 4;
        const unsigned Bb = Ab + ABUFW * 4;
        #pragma unroll
        for (int ks = 0; ks < 4; ks++) {
            unsigned a[4][4], bq[4][2];
            #pragma unroll
            for (int mf = 0; mf < 4; mf++)
                ldsm4(a[mf][0], a[mf][1], a[mf][2], a[mf][3],
                      Ab + ((wm*64 + mf*16)*KST + ks*8)*4 + aoff);
            #pragma unroll
            for (int j = 0; j < 2; j++)
                ldsm4(bq[2*j][0], bq[2*j][1], bq[2*j+1][0], bq[2*j+1][1],
                      Bb + ((wn*32 + j*16)*KST + ks*8)*4 + boff);
            #pragma unroll
            for (int mf = 0; mf < 4; mf++)
                #pragma unroll
                for (int nf = 0; nf < 4; nf++)
                    mma8(acc[mf][nf], a[mf], bq[nf]);
        }
        __syncthreads();
    }

    // epilogue: acc -> Cs, then LN (tf32-rounded store to g_q/g_k/g_v)
    float* Cs = (float*)sq;
    #pragma unroll
    for (int mf = 0; mf < 4; mf++)
        #pragma unroll
        for (int nf = 0; nf < 4; nf++) {
            int row = wm*64 + mf*16 + g, col = wn*32 + nf*8 + 2*t;
            Cs[row*CST + col]       = acc[mf][nf][0];
            Cs[row*CST + col + 1]   = acc[mf][nf][1];
            Cs[(row+8)*CST + col]   = acc[mf][nf][2];
            Cs[(row+8)*CST + col+1] = acc[mf][nf][3];
        }
    __syncthreads();

    {
        int row = tid >> 1, grp = tid & 1;
        const float* src = Cs + row*CST + grp*64;
        float sum = 0.f, sqs = 0.f;
        #pragma unroll
        for (int j = 0; j < 64; j++) { float x = src[j]; sum += x; sqs += x*x; }
        float mu = sum * (1.f/64.f);
        float var = sqs * (1.f/64.f) - mu*mu;
        float rs = rsqrtf(var + 1e-5f);
        int gm = mt*128 + row;
        int s = gm >> 12, b = (gm >> 10) & 3, n = gm & 1023;
        int tq = bn / CC;                       // 0=q,1=k,2=v (no straddle)
        int h = ((bn % CC) >> 6) + grp;
        float* dst = (tq == 0 ? g_q : tq == 1 ? g_k : g_v)
                   + ((((size_t)(s*BB+b)*HH + h)*NN + n)*HD);
        #pragma unroll
        for (int j = 0; j < 64; j += 4) {
            float4 o;
            o.x = f2tf((src[j+0]-mu)*rs*s_lng[j+0] + s_lnb[j+0]);
            o.y = f2tf((src[j+1]-mu)*rs*s_lng[j+1] + s_lnb[j+1]);
            o.z = f2tf((src[j+2]-mu)*rs*s_lng[j+2] + s_lnb[j+2]);
            o.w = f2tf((src[j+3]-mu)*rs*s_lng[j+3] + s_lnb[j+3]);
            *(float4*)(dst + j) = o;
        }
    }
}

// =====================================================================
// Kernel 2: attention (tf32 mma + ldmatrix, NO cvt in loop). 8 warps,
// q-tile 128; V staged transposed so the PV B-operand ldmatrix-loads.
// =====================================================================
#define TST 68   // 17x16B units, LDSM conflict-free

__global__ __launch_bounds__(256) void attn_mma() {
    extern __shared__ __align__(16) unsigned sa[];
    const unsigned QW = 0;
    const unsigned KW = 128*TST;
    const unsigned VW = KW + 64*TST;
    const unsigned PW = VW + 64*TST;

    const int bx = blockIdx.x;
    const int qt = bx & 7;
    const int h  = (bx >> 3) % 12;
    const int b  = (bx / 96) & 3;
    const int p  = bx / 384;
    const int qs = 1 - p, kvs = p;

    const float* qptr = g_q + (((size_t)(qs*BB+b)*HH + h)*NN + qt*128)*HD;
    const float* kptr = g_k + (((size_t)(kvs*BB+b)*HH + h)*NN)*HD;
    const float* vptr = g_v + (((size_t)(kvs*BB+b)*HH + h)*NN)*HD;

    const int tid = threadIdx.x, w = tid >> 5, lane = tid & 31;
    const int g = lane >> 2, t = lane & 3;
    const unsigned smb = s2u(sa);

    // stage Q tile (128x64) — already tf32-rounded in g_q
    #pragma unroll
    for (int i = 0; i < 8; i++) {
        int id = tid + i*256, row = id >> 4, u4 = (id & 15)*4;
        *(float4*)&sa[QW + row*TST + u4] = *(const float4*)(qptr + row*64 + u4);
    }

    const unsigned aoff = ((( lane & 15)*TST + (lane >> 4)*4))*4;
    const unsigned boff = ((((((lane >> 4) << 3)) + (lane & 7))*TST + ((lane >> 3) & 1)*4))*4;
    const unsigned Pwb = smb + (PW + w*16*TST)*4;
    const unsigned Pwidx = PW + w*16*TST;

    float o[8][4] = {};
    float m0 = -1e30f, m1 = -1e30f, l0 = 0.f, l1 = 0.f;

    for (int kc = 0; kc < 16; kc++) {
        __syncthreads();
        const float* kp = kptr + kc*64*64;
        const float* vp = vptr + kc*64*64;
        #pragma unroll
        for (int i = 0; i < 4; i++) {        // K: [kv][d]
            int id = tid + i*256, row = id >> 4, u4 = (id & 15)*4;
            *(float4*)&sa[KW + row*TST + u4] = *(const float4*)(kp + row*64 + u4);
        }
        #pragma unroll
        for (int i = 0; i < 4; i++) {        // V transposed: Vt[d][kv]
            int id = tid + i*256, d = id & 63, kvg = (id >> 6)*4;
            float4 v4;
            v4.x = vp[(kvg+0)*64 + d]; v4.y = vp[(kvg+1)*64 + d];
            v4.z = vp[(kvg+2)*64 + d]; v4.w = vp[(kvg+3)*64 + d];
            *(float4*)&sa[VW + d*TST + kvg] = v4;
        }
        __syncthreads();

        // S = Q K^T
        float s[8][4] = {};
        #pragma unroll
        for (int ks = 0; ks < 8; ks++) {
            unsigned a[4];
            ldsm4(a[0], a[1], a[2], a[3], smb + (QW + (w*16)*TST + ks*8)*4 + aoff);
            #pragma unroll
            for (int j = 0; j < 4; j++) {
                unsigned bf0[2], bf1[2];
                ldsm4(bf0[0], bf0[1], bf1[0], bf1[1],
                      smb + (KW + (j*16)*TST + ks*8)*4 + boff);
                mma8(s[2*j], a, bf0);
                mma8(s[2*j+1], a, bf1);
            }
        }

        // online softmax (warp-local; rows g and g+8)
        float mx0 = -1e30f, mx1 = -1e30f;
        #pragma unroll
        for (int nf = 0; nf < 8; nf++) {
            #pragma unroll
            for (int j = 0; j < 4; j++) s[nf][j] *= 0.125f;
            mx0 = fmaxf(mx0, fmaxf(s[nf][0], s[nf][1]));
            mx1 = fmaxf(mx1, fmaxf(s[nf][2], s[nf][3]));
        }
        mx0 = fmaxf(mx0, __shfl_xor_sync(0xffffffffu, mx0, 1));
        mx0 = fmaxf(mx0, __shfl_xor_sync(0xffffffffu, mx0, 2));
        mx1 = fmaxf(mx1, __shfl_xor_sync(0xffffffffu, mx1, 1));
        mx1 = fmaxf(mx1, __shfl_xor_sync(0xffffffffu, mx1, 2));
        float M0 = fmaxf(m0, mx0), M1 = fmaxf(m1, mx1);
        float c0 = __expf(m0 - M0), c1 = __expf(m1 - M1);
        float ls0 = 0.f, ls1 = 0.f;
        #pragma unroll
        for (int nf = 0; nf < 8; nf++) {
            float p00 = __expf(s[nf][0] - M0), p01 = __expf(s[nf][1] - M0);
            float p10 = __expf(s[nf][2] - M1), p11 = __expf(s[nf][3] - M1);
            ls0 += p00 + p01; ls1 += p10 + p11;
            unsigned idx = Pwidx + g*TST + nf*8 + 2*t;
            sa[idx]           = f2t(p00); sa[idx + 1]         = f2t(p01);
            sa[idx + 8*TST]   = f2t(p10); sa[idx + 8*TST + 1] = f2t(p11);
        }
        ls0 += __shfl_xor_sync(0xffffffffu, ls0, 1);
        ls0 += __shfl_xor_sync(0xffffffffu, ls0, 2);
        ls1 += __shfl_xor_sync(0xffffffffu, ls1, 1);
        ls1 += __shfl_xor_sync(0xffffffffu, ls1, 2);
        l0 = l0*c0 + ls0; l1 = l1*c1 + ls1;
        m0 = M0; m1 = M1;
        #pragma unroll
        for (int nf = 0; nf < 8; nf++) {
            o[nf][0] *= c0; o[nf][1] *= c0; o[nf][2] *= c1; o[nf][3] *= c1;
        }
        __syncwarp();

        // O += P @ V
        #pragma unroll
        for (int ks = 0; ks < 8; ks++) {
            unsigned a[4];
            ldsm4(a[0], a[1], a[2], a[3], Pwb + (ks*8)*4 + aoff);
            #pragma unroll
            for (int j = 0; j < 4; j++) {
                unsigned bf0[2], bf1[2];
                ldsm4(bf0[0], bf0[1], bf1[0], bf1[1],
                      smb + (VW + (j*16)*TST + ks*8)*4 + boff);
                mma8(o[2*j], a, bf0);
                mma8(o[2*j+1], a, bf1);
            }
        }
    }

    const int qrow = qt*128 + w*16;
    float inv0 = 1.f / l0, inv1 = 1.f / l1;
    float* op = g_ctx + (((size_t)(p*BB+b)*HH + h)*NN + qrow)*HD;
    #pragma unroll
    for (int nf = 0; nf < 8; nf++) {
        *(float2*)(op + g*64 + nf*8 + 2*t) =
            make_float2(f2tf(o[nf][0]*inv0), f2tf(o[nf][1]*inv0));
        *(float2*)(op + (g+8)*64 + nf*8 + 2*t) =
            make_float2(f2tf(o[nf][2]*inv1), f2tf(o[nf][3]*inv1));
    }
}

// =====================================================================
// Kernel 3: projection GEMM (NO cvt) + bias + q-residual -> d_out.
// =====================================================================
__global__ __launch_bounds__(256) void proj_gemm_mma(
    const float* __restrict__ bias, float* __restrict__ out)
{
    extern __shared__ __align__(16) unsigned sp[];
    const int tid = threadIdx.x;
    const int warp = tid >> 5, lane = tid & 31;
    const int wm = warp >> 2, wn = warp & 3;
    const int g = lane >> 2, t = lane & 3;
    const int mt = blockIdx.y;
    const int bn = blockIdx.x * 128;
    const unsigned smb = s2u(sp);

    const float* abase[4]; int au[4]; unsigned adst[4];
    const float* bsrc[4]; unsigned bdst[4];
    #pragma unroll
    for (int i = 0; i < 4; i++) {
        int c = tid + i*256, row = c >> 3, u4 = (c & 7) * 4;
        int gm = mt*128 + row;
        int pp = gm >> 12, b2 = (gm >> 10) & 3, n = gm & 1023;
        abase[i] = g_ctx + (size_t)(pp*BB + b2)*PERSB + (size_t)n*HD;
        au[i] = u4;
        adst[i] = smb + (row*KST + u4)*4;
        bsrc[i] = g_wp + (size_t)(bn + row)*CC + u4;
        bdst[i] = smb + (ABUFW + row*KST + u4)*4;
    }
    const unsigned aoff = AOFF_G(lane);
    const unsigned boff = BOFF_G(lane);

    float acc[4][4][4] = {};

    #pragma unroll
    for (int i = 0; i < 4; i++) {
        int k = au[i];
        cp16(adst[i], abase[i] + (k >> 6)*(NN*HD) + (k & 63));
        cp16(bdst[i], bsrc[i]);
    }
    CPCOMMIT();

    for (int kt = 0; kt < 24; kt++) {
        if (kt < 23) {
            unsigned bo = ((kt+1) & 1) * BUFW * 4;
            #pragma unroll
            for (int i = 0; i < 4; i++) {
                int k = (kt+1)*32 + au[i];
                cp16(adst[i] + bo, abase[i] + (k >> 6)*(NN*HD) + (k & 63));
                cp16(bdst[i] + bo, bsrc[i] + (kt+1)*32);
            }
            CPCOMMIT();
            asm volatile("cp.async.wait_group 1;");
        } else {
            asm volatile("cp.async.wait_group 0;");
        }
        __syncthreads();
        const unsigned Ab = smb + (kt & 1) * BUFW * 4;
        const unsigned Bb = Ab + ABUFW * 4;
        #pragma unroll
        for (int ks = 0; ks < 4; ks++) {
            unsigned a[4][4], bq[4][2];
            #pragma unroll
            for (int mf = 0; mf < 4; mf++)
                ldsm4(a[mf][0], a[mf][1], a[mf][2], a[mf][3],
                      Ab + ((wm*64 + mf*16)*KST + ks*8)*4 + aoff);
            #pragma unroll
            for (int j = 0; j < 2; j++)
                ldsm4(bq[2*j][0], bq[2*j][1], bq[2*j+1][0], bq[2*j+1][1],
                      Bb + ((wn*32 + j*16)*KST + ks*8)*4 + boff);
            #pragma unroll
            for (int mf = 0; mf < 4; mf++)
                #pragma unroll
                for (int nf = 0; nf < 4; nf++)
                    mma8(acc[mf][nf], a[mf], bq[nf]);
        }
        __syncthreads();
    }

    // epilogue: bias + flat-q residual -> d_out
    #pragma unroll
    for (int mf = 0; mf < 4; mf++) {
        #pragma unroll
        for (int rr = 0; rr < 2; rr++) {
            int gm = mt*128 + wm*64 + mf*16 + g + rr*8;
            int pp = gm >> 12, b2 = (gm >> 10) & 3, n = gm & 1023;
            const float* qres = g_q + (size_t)((1-pp)*BB + b2)*PERSB + (size_t)n*CC;
            #pragma unroll
            for (int nf = 0; nf < 4; nf++) {
                int col = bn + wn*32 + nf*8 + 2*t;
                float2 r;
                r.x = acc[mf][nf][2*rr+0] + __ldg(bias + col)   + __ldg(qres + col);
                r.y = acc[mf][nf][2*rr+1] + __ldg(bias + col+1) + __ldg(qres + col+1);
                *(float2*)(out + (size_t)gm*CC + col) = r;
            }
        }
    }
}

// =====================================================================
extern "C" void kernel_launch(void* const* d_in, const int* in_sizes, int n_in,
                              void* d_out, int out_size) {
    const float* before = (const float*)d_in[0];
    const float* after  = (const float*)d_in[1];
    const float* W_qkv  = (const float*)d_in[2];
    const float* ln_g   = (const float*)d_in[3];
    const float* ln_b   = (const float*)d_in[4];
    const float* W_proj = (const float*)d_in[5];
    const float* b_proj = (const float*)d_in[6];
    float* out = (float*)d_out;

    const int gemm_smem = 2 * BUFW * 4;                                 // 73728 B
    const int attn_smem = (128*TST + 64*TST + 64*TST + 8*16*TST) * 4;   // 104448 B

    // 0) pre-round inputs to tf32
    preround_kernel<<<PRTOT/256, 256>>>(before, after, W_qkv, W_proj);

    // 1) QKV GEMM + fused LN: grid (2304/128, 8192/128)
    {
        cudaFuncSetAttribute(qkv_gemm_mma, cudaFuncAttributeMaxDynamicSharedMemorySize, gemm_smem);
        dim3 grid(QKV3/128, MROWS/128);
        qkv_gemm_mma<<<grid, 256, gemm_smem>>>(ln_g, ln_b);
    }
    // 2) Attention: 2*4*12*8 = 768 blocks
    {
        cudaFuncSetAttribute(attn_mma, cudaFuncAttributeMaxDynamicSharedMemorySize, attn_smem);
        attn_mma<<<768, 256, attn_smem>>>();
    }
    // 3) Projection GEMM: grid (768/128, 8192/128)
    {
        cudaFuncSetAttribute(proj_gemm_mma, cudaFuncAttributeMaxDynamicSharedMemorySize, gemm_smem);
        dim3 grid(CC/128, MROWS/128);
        proj_gemm_mma<<<grid, 256, gemm_smem>>>(b_proj, out);
    }
}

// round 6
// speedup vs baseline: 1.4785x; 1.4785x over previous
#include <cuda_runtime.h>
#include <math.h>

#define BB 4
#define NN 1024
#define CC 768
#define HH 12
#define HD 64
#define QKV3 (3*CC)          // 2304
#define MROWS (2*BB*NN)      // 8192
#define PERSB (HH*NN*HD)     // 786432 floats per (stream,b)

// -------- scratch (device globals; no allocation) --------
__device__ float g_q  [2*BB*HH*NN*HD];   // [s][b][h][n][d]  (tf32-rounded)
__device__ float g_k  [2*BB*HH*NN*HD];   // [s][b][h][n][d]
__device__ float g_v  [2*BB*HH*NN*HD];   // [s][b][h][d][n]  (TRANSPOSED)
__device__ float g_ctx[2*BB*HH*NN*HD];   // [p][b][h][n][d]
__device__ float g_x  [MROWS*CC];        // rounded [before;after]
__device__ float g_wq [QKV3*CC];         // rounded W_qkv
__device__ float g_wp [CC*CC];           // rounded W_proj

// -------- helpers --------
__device__ __forceinline__ unsigned f2t(float x) {
    unsigned u; asm("cvt.rna.tf32.f32 %0, %1;" : "=r"(u) : "f"(x)); return u;
}
__device__ __forceinline__ float f2tf(float x) { return __uint_as_float(f2t(x)); }
__device__ __forceinline__ void mma8(float* c, const unsigned* a, const unsigned* b) {
    asm volatile("mma.sync.aligned.m16n8k8.row.col.f32.tf32.tf32.f32 "
        "{%0,%1,%2,%3}, {%4,%5,%6,%7}, {%8,%9}, {%0,%1,%2,%3};"
        : "+f"(c[0]), "+f"(c[1]), "+f"(c[2]), "+f"(c[3])
        : "r"(a[0]), "r"(a[1]), "r"(a[2]), "r"(a[3]), "r"(b[0]), "r"(b[1]));
}
__device__ __forceinline__ void ldsm4(unsigned& r0, unsigned& r1, unsigned& r2,
                                      unsigned& r3, unsigned addr) {
    asm volatile("ldmatrix.sync.aligned.m8n8.x4.shared.b16 {%0,%1,%2,%3}, [%4];"
        : "=r"(r0), "=r"(r1), "=r"(r2), "=r"(r3) : "r"(addr));
}
__device__ __forceinline__ unsigned s2u(const void* p) {
    return (unsigned)__cvta_generic_to_shared(p);
}
__device__ __forceinline__ void cp16(unsigned dst, const float* src) {
    asm volatile("cp.async.cg.shared.global [%0], [%1], 16;" :: "r"(dst), "l"(src));
}
#define CPCOMMIT() asm volatile("cp.async.commit_group;")

// GEMM tiling (qkv & proj): 128x128 block, K-step 32, 8 warps (2x4), 3-stage
#define KST 36               // smem row stride (words), LDSM conflict-free
#define ABUFW (128*KST)      // words per A tile
#define BUFW  (2*ABUFW)      // words per stage (A + B)
#define BUFB  (BUFW*4)       // bytes per stage
#define CST 133              // epilogue C stride

#define AOFF_G(lane) ((((lane)&15)*KST + ((lane)>>4)*4)*4)
#define BOFF_G(lane) (((((((lane)>>4)<<3)) + ((lane)&7))*KST + (((lane)>>3)&1)*4)*4)

// =====================================================================
// Kernel 0: pre-round inputs to tf32 (once).
// =====================================================================
#define XQ4 (MROWS*CC/4)
#define WQ4 (QKV3*CC/4)
#define PQ4 (CC*CC/4)
#define PRTOT (XQ4+WQ4+PQ4)

__global__ __launch_bounds__(256) void preround_kernel(
    const float* __restrict__ before, const float* __restrict__ after,
    const float* __restrict__ Wqkv, const float* __restrict__ Wp)
{
    int i = blockIdx.x*256 + threadIdx.x;
    float4 v; float* dst;
    if (i < XQ4) {
        v = (i < XQ4/2) ? ((const float4*)before)[i]
                        : ((const float4*)after)[i - XQ4/2];
        dst = g_x + (size_t)i*4;
    } else if (i < XQ4 + WQ4) {
        v = ((const float4*)Wqkv)[i - XQ4];
        dst = g_wq + (size_t)(i - XQ4)*4;
    } else {
        v = ((const float4*)Wp)[i - XQ4 - WQ4];
        dst = g_wp + (size_t)(i - XQ4 - WQ4)*4;
    }
    float4 o;
    o.x = f2tf(v.x); o.y = f2tf(v.y); o.z = f2tf(v.z); o.w = f2tf(v.w);
    *(float4*)dst = o;
}

// =====================================================================
// Kernel 1: QKV GEMM (3-stage cp.async, 1 sync/iter) + fused LN.
// =====================================================================
__global__ __launch_bounds__(256) void qkv_gemm_mma(
    const float* __restrict__ ln_g, const float* __restrict__ ln_b)
{
    extern __shared__ __align__(16) unsigned sq[];   // 3*BUFW words
    __shared__ float s_lng[64], s_lnb[64];
    const int tid = threadIdx.x;
    if (tid < 64) { s_lng[tid] = ln_g[tid]; s_lnb[tid] = ln_b[tid]; }

    const int warp = tid >> 5, lane = tid & 31;
    const int wm = warp >> 2, wn = warp & 3;
    const int g = lane >> 2, t = lane & 3;
    const int mt = blockIdx.y;
    const int bn = blockIdx.x * 128;
    const unsigned smb = s2u(sq);

    const float* asrc[4]; unsigned adst[4];
    const float* bsrc[4]; unsigned bdst[4];
    #pragma unroll
    for (int i = 0; i < 4; i++) {
        int c = tid + i*256, row = c >> 3, u4 = (c & 7) * 4;
        asrc[i] = g_x + (size_t)(mt*128 + row)*CC + u4;
        adst[i] = smb + (row*KST + u4)*4;
        bsrc[i] = g_wq + (size_t)(bn + row)*CC + u4;
        bdst[i] = smb + (ABUFW + row*KST + u4)*4;
    }
    const unsigned aoff = AOFF_G(lane);
    const unsigned boff = BOFF_G(lane);

    float acc[4][4][4] = {};

    #pragma unroll
    for (int i = 0; i < 4; i++) { cp16(adst[i], asrc[i]); cp16(bdst[i], bsrc[i]); }
    CPCOMMIT();
    #pragma unroll
    for (int i = 0; i < 4; i++) { cp16(adst[i]+BUFB, asrc[i]+32); cp16(bdst[i]+BUFB, bsrc[i]+32); }
    CPCOMMIT();

    unsigned rdo = 0, wro = 2*BUFB;
    for (int kt = 0; kt < 24; kt++) {
        if (kt < 23) { asm volatile("cp.async.wait_group 1;"); }
        else         { asm volatile("cp.async.wait_group 0;"); }
        __syncthreads();
        if (kt < 22) {
            #pragma unroll
            for (int i = 0; i < 4; i++) {
                cp16(adst[i] + wro, asrc[i] + (kt+2)*32);
                cp16(bdst[i] + wro, bsrc[i] + (kt+2)*32);
            }
            CPCOMMIT();
            wro += BUFB; if (wro == 3*BUFB) wro = 0;
        }
        const unsigned Ab = smb + rdo;
        const unsigned Bb = Ab + ABUFW*4;
        rdo += BUFB; if (rdo == 3*BUFB) rdo = 0;
        #pragma unroll
        for (int ks = 0; ks < 4; ks++) {
            unsigned a[4][4], bq[4][2];
            #pragma unroll
            for (int mf = 0; mf < 4; mf++)
                ldsm4(a[mf][0], a[mf][1], a[mf][2], a[mf][3],
                      Ab + ((wm*64 + mf*16)*KST + ks*8)*4 + aoff);
            #pragma unroll
            for (int j = 0; j < 2; j++)
                ldsm4(bq[2*j][0], bq[2*j][1], bq[2*j+1][0], bq[2*j+1][1],
                      Bb + ((wn*32 + j*16)*KST + ks*8)*4 + boff);
            #pragma unroll
            for (int mf = 0; mf < 4; mf++)
                #pragma unroll
                for (int nf = 0; nf < 4; nf++)
                    mma8(acc[mf][nf], a[mf], bq[nf]);
        }
    }
    __syncthreads();   // all warps done before Cs aliases the buffers

    float* Cs = (float*)sq;
    #pragma unroll
    for (int mf = 0; mf < 4; mf++)
        #pragma unroll
        for (int nf = 0; nf < 4; nf++) {
            int row = wm*64 + mf*16 + g, col = wn*32 + nf*8 + 2*t;
            Cs[row*CST + col]       = acc[mf][nf][0];
            Cs[row*CST + col + 1]   = acc[mf][nf][1];
            Cs[(row+8)*CST + col]   = acc[mf][nf][2];
            Cs[(row+8)*CST + col+1] = acc[mf][nf][3];
        }
    __syncthreads();

    {   // LayerNorm over head_dim=64 (2 head-groups per 128-col tile)
        int row = tid >> 1, grp = tid & 1;
        const float* src = Cs + row*CST + grp*64;
        float sum = 0.f, sqs = 0.f;
        #pragma unroll
        for (int j = 0; j < 64; j++) { float x = src[j]; sum += x; sqs += x*x; }
        float mu = sum * (1.f/64.f);
        float var = sqs * (1.f/64.f) - mu*mu;
        float rs = rsqrtf(var + 1e-5f);
        int gm = mt*128 + row;
        int s = gm >> 12, b = (gm >> 10) & 3, n = gm & 1023;
        int tq = bn / CC;                       // 0=q,1=k,2=v
        int h = ((bn % CC) >> 6) + grp;
        if (tq < 2) {
            float* dst = (tq == 0 ? g_q : g_k)
                       + ((((size_t)(s*BB+b)*HH + h)*NN + n)*HD);
            #pragma unroll
            for (int j = 0; j < 64; j += 4) {
                float4 o;
                o.x = f2tf((src[j+0]-mu)*rs*s_lng[j+0] + s_lnb[j+0]);
                o.y = f2tf((src[j+1]-mu)*rs*s_lng[j+1] + s_lnb[j+1]);
                o.z = f2tf((src[j+2]-mu)*rs*s_lng[j+2] + s_lnb[j+2]);
                o.w = f2tf((src[j+3]-mu)*rs*s_lng[j+3] + s_lnb[j+3]);
                *(float4*)(dst + j) = o;
            }
        } else {
            // V stored TRANSPOSED: g_v[s][b][h][d][n]
            float* dstT = g_v + (((size_t)(s*BB+b)*HH + h)*HD)*NN + n;
            #pragma unroll
            for (int j = 0; j < 64; j++)
                dstT[(size_t)j*NN] = f2tf((src[j]-mu)*rs*s_lng[j] + s_lnb[j]);
        }
    }
}

// =====================================================================
// Kernel 2: attention (tf32 mma + ldmatrix + cp.async K/V prefetch).
// 256 thr = 8 warps, q-tile 128; V already transposed in global.
// =====================================================================
#define TST 68   // 17x16B units, LDSM conflict-free

__global__ __launch_bounds__(256) void attn_mma() {
    extern __shared__ __align__(16) unsigned sa[];
    const unsigned QW  = 0;
    const unsigned KW0 = 128*TST;             // 2 x 64*TST K buffers
    const unsigned VW0 = KW0 + 2*64*TST;      // 2 x 64*TST Vt buffers
    const unsigned PW  = VW0 + 2*64*TST;

    const int bx = blockIdx.x;
    const int qt = bx & 7;
    const int h  = (bx >> 3) % 12;
    const int b  = (bx / 96) & 3;
    const int p  = bx / 384;
    const int qs = 1 - p, kvs = p;

    const float* qptr  = g_q + (((size_t)(qs*BB+b)*HH + h)*NN + qt*128)*HD;
    const float* kptr  = g_k + (((size_t)(kvs*BB+b)*HH + h)*NN)*HD;
    const float* vptrT = g_v + (((size_t)(kvs*BB+b)*HH + h)*HD)*NN;   // [d][n]

    const int tid = threadIdx.x, w = tid >> 5, lane = tid & 31;
    const int g = lane >> 2, t = lane & 3;
    const unsigned smb = s2u(sa);

    // stage Q tile (128x64) — already tf32-rounded
    #pragma unroll
    for (int i = 0; i < 8; i++) {
        int id = tid + i*256, row = id >> 4, u4 = (id & 15)*4;
        *(float4*)&sa[QW + row*TST + u4] = *(const float4*)(qptr + row*64 + u4);
    }

    const unsigned aoff = (((lane & 15)*TST + (lane >> 4)*4))*4;
    const unsigned boff = ((((((lane >> 4) << 3)) + (lane & 7))*TST + ((lane >> 3) & 1)*4))*4;
    const unsigned Pwb = smb + (PW + w*16*TST)*4;
    const unsigned Pwidx = PW + w*16*TST;

    // per-thread staging coords (4 cp16 for K, 4 cp16 for Vt)
    int srow[4], su4[4];
    #pragma unroll
    for (int i = 0; i < 4; i++) {
        int id = tid + i*256; srow[i] = id >> 4; su4[i] = (id & 15)*4;
    }

    // prefetch kc=0 into buffer 0
    #pragma unroll
    for (int i = 0; i < 4; i++) {
        cp16(smb + (KW0 + srow[i]*TST + su4[i])*4, kptr + srow[i]*64 + su4[i]);
        cp16(smb + (VW0 + srow[i]*TST + su4[i])*4, vptrT + (size_t)srow[i]*NN + su4[i]);
    }
    CPCOMMIT();

    float o[8][4] = {};
    float m0 = -1e30f, m1 = -1e30f, l0 = 0.f, l1 = 0.f;

    for (int kc = 0; kc < 16; kc++) {
        __syncthreads();                   // prev-iter reads of buf[(kc+1)&1] done (and Q at kc=0)
        if (kc < 15) {
            const float* kp = kptr + (kc+1)*64*64;
            const unsigned kb = smb + (KW0 + ((kc+1)&1)*64*TST)*4;
            const unsigned vb = smb + (VW0 + ((kc+1)&1)*64*TST)*4;
            #pragma unroll
            for (int i = 0; i < 4; i++) {
                cp16(kb + (srow[i]*TST + su4[i])*4, kp + srow[i]*64 + su4[i]);
                cp16(vb + (srow[i]*TST + su4[i])*4,
                     vptrT + (size_t)srow[i]*NN + (kc+1)*64 + su4[i]);
            }
            CPCOMMIT();
            asm volatile("cp.async.wait_group 1;");
        } else {
            asm volatile("cp.async.wait_group 0;");
        }
        __syncthreads();                   // buf[kc&1] visible to all

        const unsigned KWb = KW0 + (kc&1)*64*TST;
        const unsigned VWb = VW0 + (kc&1)*64*TST;

        // S = Q K^T
        float s[8][4] = {};
        #pragma unroll
        for (int ks = 0; ks < 8; ks++) {
            unsigned a[4];
            ldsm4(a[0], a[1], a[2], a[3], smb + (QW + (w*16)*TST + ks*8)*4 + aoff);
            #pragma unroll
            for (int j = 0; j < 4; j++) {
                unsigned bf0[2], bf1[2];
                ldsm4(bf0[0], bf0[1], bf1[0], bf1[1],
                      smb + (KWb + (j*16)*TST + ks*8)*4 + boff);
                mma8(s[2*j], a, bf0);
                mma8(s[2*j+1], a, bf1);
            }
        }

        // online softmax (warp-local; rows g and g+8)
        float mx0 = -1e30f, mx1 = -1e30f;
        #pragma unroll
        for (int nf = 0; nf < 8; nf++) {
            #pragma unroll
            for (int j = 0; j < 4; j++) s[nf][j] *= 0.125f;
            mx0 = fmaxf(mx0, fmaxf(s[nf][0], s[nf][1]));
            mx1 = fmaxf(mx1, fmaxf(s[nf][2], s[nf][3]));
        }
        mx0 = fmaxf(mx0, __shfl_xor_sync(0xffffffffu, mx0, 1));
        mx0 = fmaxf(mx0, __shfl_xor_sync(0xffffffffu, mx0, 2));
        mx1 = fmaxf(mx1, __shfl_xor_sync(0xffffffffu, mx1, 1));
        mx1 = fmaxf(mx1, __shfl_xor_sync(0xffffffffu, mx1, 2));
        float M0 = fmaxf(m0, mx0), M1 = fmaxf(m1, mx1);
        float c0 = __expf(m0 - M0), c1 = __expf(m1 - M1);
        float ls0 = 0.f, ls1 = 0.f;
        #pragma unroll
        for (int nf = 0; nf < 8; nf++) {
            float p00 = __expf(s[nf][0] - M0), p01 = __expf(s[nf][1] - M0);
            float p10 = __expf(s[nf][2] - M1), p11 = __expf(s[nf][3] - M1);
            ls0 += p00 + p01; ls1 += p10 + p11;
            unsigned idx = Pwidx + g*TST + nf*8 + 2*t;
            sa[idx]           = f2t(p00); sa[idx + 1]         = f2t(p01);
            sa[idx + 8*TST]   = f2t(p10); sa[idx + 8*TST + 1] = f2t(p11);
        }
        ls0 += __shfl_xor_sync(0xffffffffu, ls0, 1);
        ls0 += __shfl_xor_sync(0xffffffffu, ls0, 2);
        ls1 += __shfl_xor_sync(0xffffffffu, ls1, 1);
        ls1 += __shfl_xor_sync(0xffffffffu, ls1, 2);
        l0 = l0*c0 + ls0; l1 = l1*c1 + ls1;
        m0 = M0; m1 = M1;
        #pragma unroll
        for (int nf = 0; nf < 8; nf++) {
            o[nf][0] *= c0; o[nf][1] *= c0; o[nf][2] *= c1; o[nf][3] *= c1;
        }
        __syncwarp();

        // O += P @ V
        #pragma unroll
        for (int ks = 0; ks < 8; ks++) {
            unsigned a[4];
            ldsm4(a[0], a[1], a[2], a[3], Pwb + (ks*8)*4 + aoff);
            #pragma unroll
            for (int j = 0; j < 4; j++) {
                unsigned bf0[2], bf1[2];
                ldsm4(bf0[0], bf0[1], bf1[0], bf1[1],
                      smb + (VWb + (j*16)*TST + ks*8)*4 + boff);
                mma8(o[2*j], a, bf0);
                mma8(o[2*j+1], a, bf1);
            }
        }
    }

    const int qrow = qt*128 + w*16;
    float inv0 = 1.f / l0, inv1 = 1.f / l1;
    float* op = g_ctx + (((size_t)(p*BB+b)*HH + h)*NN + qrow)*HD;
    #pragma unroll
    for (int nf = 0; nf < 8; nf++) {
        *(float2*)(op + g*64 + nf*8 + 2*t) =
            make_float2(f2tf(o[nf][0]*inv0), f2tf(o[nf][1]*inv0));
        *(float2*)(op + (g+8)*64 + nf*8 + 2*t) =
            make_float2(f2tf(o[nf][2]*inv1), f2tf(o[nf][3]*inv1));
    }
}

// =====================================================================
// Kernel 3: projection GEMM (3-stage, 1 sync/iter) + bias + q-residual.
// =====================================================================
__global__ __launch_bounds__(256) void proj_gemm_mma(
    const float* __restrict__ bias, float* __restrict__ out)
{
    extern __shared__ __align__(16) unsigned sp[];
    const int tid = threadIdx.x;
    const int warp = tid >> 5, lane = tid & 31;
    const int wm = warp >> 2, wn = warp & 3;
    const int g = lane >> 2, t = lane & 3;
    const int mt = blockIdx.y;
    const int bn = blockIdx.x * 128;
    const unsigned smb = s2u(sp);

    const float* abase[4]; int au[4]; unsigned adst[4];
    const float* bsrc[4]; unsigned bdst[4];
    #pragma unroll
    for (int i = 0; i < 4; i++) {
        int c = tid + i*256, row = c >> 3, u4 = (c & 7) * 4;
        int gm = mt*128 + row;
        int pp = gm >> 12, b2 = (gm >> 10) & 3, n = gm & 1023;
        abase[i] = g_ctx + (size_t)(pp*BB + b2)*PERSB + (size_t)n*HD;
        au[i] = u4;
        adst[i] = smb + (row*KST + u4)*4;
        bsrc[i] = g_wp + (size_t)(bn + row)*CC + u4;
        bdst[i] = smb + (ABUFW + row*KST + u4)*4;
    }
    const unsigned aoff = AOFF_G(lane);
    const unsigned boff = BOFF_G(lane);

    float acc[4][4][4] = {};

    #pragma unroll
    for (int i = 0; i < 4; i++) {
        cp16(adst[i], abase[i] + (au[i] >> 6)*(NN*HD) + (au[i] & 63));
        cp16(bdst[i], bsrc[i]);
    }
    CPCOMMIT();
    #pragma unroll
    for (int i = 0; i < 4; i++) {
        int k = 32 + au[i];
        cp16(adst[i]+BUFB, abase[i] + (k >> 6)*(NN*HD) + (k & 63));
        cp16(bdst[i]+BUFB, bsrc[i] + 32);
    }
    CPCOMMIT();

    unsigned rdo = 0, wro = 2*BUFB;
    for (int kt = 0; kt < 24; kt++) {
        if (kt < 23) { asm volatile("cp.async.wait_group 1;"); }
        else         { asm volatile("cp.async.wait_group 0;"); }
        __syncthreads();
        if (kt < 22) {
            #pragma unroll
            for (int i = 0; i < 4; i++) {
                int k = (kt+2)*32 + au[i];
                cp16(adst[i] + wro, abase[i] + (k >> 6)*(NN*HD) + (k & 63));
                cp16(bdst[i] + wro, bsrc[i] + (kt+2)*32);
            }
            CPCOMMIT();
            wro += BUFB; if (wro == 3*BUFB) wro = 0;
        }
        const unsigned Ab = smb + rdo;
        const unsigned Bb = Ab + ABUFW*4;
        rdo += BUFB; if (rdo == 3*BUFB) rdo = 0;
        #pragma unroll
        for (int ks = 0; ks < 4; ks++) {
            unsigned a[4][4], bq[4][2];
            #pragma unroll
            for (int mf = 0; mf < 4; mf++)
                ldsm4(a[mf][0], a[mf][1], a[mf][2], a[mf][3],
                      Ab + ((wm*64 + mf*16)*KST + ks*8)*4 + aoff);
            #pragma unroll
            for (int j = 0; j < 2; j++)
                ldsm4(bq[2*j][0], bq[2*j][1], bq[2*j+1][0], bq[2*j+1][1],
                      Bb + ((wn*32 + j*16)*KST + ks*8)*4 + boff);
            #pragma unroll
            for (int mf = 0; mf < 4; mf++)
                #pragma unroll
                for (int nf = 0; nf < 4; nf++)
                    mma8(acc[mf][nf], a[mf], bq[nf]);
        }
    }

    // epilogue: bias + flat-q residual -> d_out
    #pragma unroll
    for (int mf = 0; mf < 4; mf++) {
        #pragma unroll
        for (int rr = 0; rr < 2; rr++) {
            int gm = mt*128 + wm*64 + mf*16 + g + rr*8;
            int pp = gm >> 12, b2 = (gm >> 10) & 3, n = gm & 1023;
            const float* qres = g_q + (size_t)((1-pp)*BB + b2)*PERSB + (size_t)n*CC;
            #pragma unroll
            for (int nf = 0; nf < 4; nf++) {
                int col = bn + wn*32 + nf*8 + 2*t;
                float2 r;
                r.x = acc[mf][nf][2*rr+0] + __ldg(bias + col)   + __ldg(qres + col);
                r.y = acc[mf][nf][2*rr+1] + __ldg(bias + col+1) + __ldg(qres + col+1);
                *(float2*)(out + (size_t)gm*CC + col) = r;
            }
        }
    }
}

// =====================================================================
extern "C" void kernel_launch(void* const* d_in, const int* in_sizes, int n_in,
                              void* d_out, int out_size) {
    const float* before = (const float*)d_in[0];
    const float* after  = (const float*)d_in[1];
    const float* W_qkv  = (const float*)d_in[2];
    const float* ln_g   = (const float*)d_in[3];
    const float* ln_b   = (const float*)d_in[4];
    const float* W_proj = (const float*)d_in[5];
    const float* b_proj = (const float*)d_in[6];
    float* out = (float*)d_out;

    const int gemm_smem = 3 * BUFB;                    // 110592 B
    const int attn_smem = (128*TST + 4*64*TST + 8*16*TST) * 4;   // 139264 B

    // 0) pre-round inputs to tf32
    preround_kernel<<<PRTOT/256, 256>>>(before, after, W_qkv, W_proj);

    // 1) QKV GEMM + fused LN
    {
        cudaFuncSetAttribute(qkv_gemm_mma, cudaFuncAttributeMaxDynamicSharedMemorySize, gemm_smem);
        dim3 grid(QKV3/128, MROWS/128);
        qkv_gemm_mma<<<grid, 256, gemm_smem>>>(ln_g, ln_b);
    }
    // 2) Attention: 768 blocks
    {
        cudaFuncSetAttribute(attn_mma, cudaFuncAttributeMaxDynamicSharedMemorySize, attn_smem);
        attn_mma<<<768, 256, attn_smem>>>();
    }
    // 3) Projection GEMM
    {
        cudaFuncSetAttribute(proj_gemm_mma, cudaFuncAttributeMaxDynamicSharedMemorySize, gemm_smem);
        dim3 grid(CC/128, MROWS/128);
        proj_gemm_mma<<<grid, 256, gemm_smem>>>(b_proj, out);
    }
}

// round 7
// speedup vs baseline: 1.7061x; 1.1539x over previous
#include <cuda_runtime.h>
#include <math.h>

#define BB 4
#define NN 1024
#define CC 768
#define HH 12
#define HD 64
#define QKV3 (3*CC)          // 2304
#define MROWS (2*BB*NN)      // 8192
#define PERSB (HH*NN*HD)     // 786432 floats per (stream,b)

// -------- scratch (device globals; no allocation) --------
__device__ float g_q  [2*BB*HH*NN*HD];   // [s][b][h][n][d]  (tf32-rounded)
__device__ float g_k  [2*BB*HH*NN*HD];   // [s][b][h][n][d]
__device__ float g_v  [2*BB*HH*NN*HD];   // [s][b][h][d][n]  (TRANSPOSED)
__device__ float g_ctx[2*BB*HH*NN*HD];   // [p][b][h][n][d]
__device__ float g_x  [MROWS*CC];        // rounded [before;after]
__device__ float g_wq [QKV3*CC];         // rounded W_qkv
__device__ float g_wp [CC*CC];           // rounded W_proj

// -------- helpers --------
__device__ __forceinline__ unsigned f2t(float x) {
    unsigned u; asm("cvt.rna.tf32.f32 %0, %1;" : "=r"(u) : "f"(x)); return u;
}
__device__ __forceinline__ float f2tf(float x) { return __uint_as_float(f2t(x)); }
__device__ __forceinline__ float ex2f(float x) {
    float y; asm("ex2.approx.ftz.f32 %0, %1;" : "=f"(y) : "f"(x)); return y;
}
__device__ __forceinline__ void mma8(float* c, const unsigned* a, const unsigned* b) {
    asm volatile("mma.sync.aligned.m16n8k8.row.col.f32.tf32.tf32.f32 "
        "{%0,%1,%2,%3}, {%4,%5,%6,%7}, {%8,%9}, {%0,%1,%2,%3};"
        : "+f"(c[0]), "+f"(c[1]), "+f"(c[2]), "+f"(c[3])
        : "r"(a[0]), "r"(a[1]), "r"(a[2]), "r"(a[3]), "r"(b[0]), "r"(b[1]));
}
__device__ __forceinline__ void ldsm4(unsigned& r0, unsigned& r1, unsigned& r2,
                                      unsigned& r3, unsigned addr) {
    asm volatile("ldmatrix.sync.aligned.m8n8.x4.shared.b16 {%0,%1,%2,%3}, [%4];"
        : "=r"(r0), "=r"(r1), "=r"(r2), "=r"(r3) : "r"(addr));
}
__device__ __forceinline__ unsigned s2u(const void* p) {
    return (unsigned)__cvta_generic_to_shared(p);
}
__device__ __forceinline__ void cp16(unsigned dst, const float* src) {
    asm volatile("cp.async.cg.shared.global [%0], [%1], 16;" :: "r"(dst), "l"(src));
}
#define CPCOMMIT() asm volatile("cp.async.commit_group;")

// GEMM tiling (qkv & proj): 128x128 block, K-step 32, 8 warps (2x4), 3-stage
#define KST 36
#define ABUFW (128*KST)
#define BUFW  (2*ABUFW)
#define BUFB  (BUFW*4)
#define CST 133

#define AOFF_G(lane) ((((lane)&15)*KST + ((lane)>>4)*4)*4)
#define BOFF_G(lane) (((((((lane)>>4)<<3)) + ((lane)&7))*KST + (((lane)>>3)&1)*4)*4)

// =====================================================================
// Kernel 0: pre-round inputs to tf32 (once).
// =====================================================================
#define XQ4 (MROWS*CC/4)
#define WQ4 (QKV3*CC/4)
#define PQ4 (CC*CC/4)
#define PRTOT (XQ4+WQ4+PQ4)

__global__ __launch_bounds__(256) void preround_kernel(
    const float* __restrict__ before, const float* __restrict__ after,
    const float* __restrict__ Wqkv, const float* __restrict__ Wp)
{
    int i = blockIdx.x*256 + threadIdx.x;
    float4 v; float* dst;
    if (i < XQ4) {
        v = (i < XQ4/2) ? ((const float4*)before)[i]
                        : ((const float4*)after)[i - XQ4/2];
        dst = g_x + (size_t)i*4;
    } else if (i < XQ4 + WQ4) {
        v = ((const float4*)Wqkv)[i - XQ4];
        dst = g_wq + (size_t)(i - XQ4)*4;
    } else {
        v = ((const float4*)Wp)[i - XQ4 - WQ4];
        dst = g_wp + (size_t)(i - XQ4 - WQ4)*4;
    }
    float4 o;
    o.x = f2tf(v.x); o.y = f2tf(v.y); o.z = f2tf(v.z); o.w = f2tf(v.w);
    *(float4*)dst = o;
}

// =====================================================================
// Kernel 1: QKV GEMM (3-stage cp.async, 1 sync/iter) + fused LN.
// =====================================================================
__global__ __launch_bounds__(256, 2) void qkv_gemm_mma(
    const float* __restrict__ ln_g, const float* __restrict__ ln_b)
{
    extern __shared__ __align__(16) unsigned sq[];
    __shared__ float s_lng[64], s_lnb[64];
    const int tid = threadIdx.x;
    if (tid < 64) { s_lng[tid] = ln_g[tid]; s_lnb[tid] = ln_b[tid]; }

    const int warp = tid >> 5, lane = tid & 31;
    const int wm = warp >> 2, wn = warp & 3;
    const int g = lane >> 2, t = lane & 3;
    const int mt = blockIdx.y;
    const int bn = blockIdx.x * 128;
    const unsigned smb = s2u(sq);

    const float* asrc[4]; unsigned adst[4];
    const float* bsrc[4]; unsigned bdst[4];
    #pragma unroll
    for (int i = 0; i < 4; i++) {
        int c = tid + i*256, row = c >> 3, u4 = (c & 7) * 4;
        asrc[i] = g_x + (size_t)(mt*128 + row)*CC + u4;
        adst[i] = smb + (row*KST + u4)*4;
        bsrc[i] = g_wq + (size_t)(bn + row)*CC + u4;
        bdst[i] = smb + (ABUFW + row*KST + u4)*4;
    }
    const unsigned aoff = AOFF_G(lane);
    const unsigned boff = BOFF_G(lane);

    float acc[4][4][4] = {};

    #pragma unroll
    for (int i = 0; i < 4; i++) { cp16(adst[i], asrc[i]); cp16(bdst[i], bsrc[i]); }
    CPCOMMIT();
    #pragma unroll
    for (int i = 0; i < 4; i++) { cp16(adst[i]+BUFB, asrc[i]+32); cp16(bdst[i]+BUFB, bsrc[i]+32); }
    CPCOMMIT();

    unsigned rdo = 0, wro = 2*BUFB;
    for (int kt = 0; kt < 24; kt++) {
        if (kt < 23) { asm volatile("cp.async.wait_group 1;"); }
        else         { asm volatile("cp.async.wait_group 0;"); }
        __syncthreads();
        if (kt < 22) {
            #pragma unroll
            for (int i = 0; i < 4; i++) {
                cp16(adst[i] + wro, asrc[i] + (kt+2)*32);
                cp16(bdst[i] + wro, bsrc[i] + (kt+2)*32);
            }
            CPCOMMIT();
            wro += BUFB; if (wro == 3*BUFB) wro = 0;
        }
        const unsigned Ab = smb + rdo;
        const unsigned Bb = Ab + ABUFW*4;
        rdo += BUFB; if (rdo == 3*BUFB) rdo = 0;
        #pragma unroll
        for (int ks = 0; ks < 4; ks++) {
            unsigned a[4][4], bq[4][2];
            #pragma unroll
            for (int mf = 0; mf < 4; mf++)
                ldsm4(a[mf][0], a[mf][1], a[mf][2], a[mf][3],
                      Ab + ((wm*64 + mf*16)*KST + ks*8)*4 + aoff);
            #pragma unroll
            for (int j = 0; j < 2; j++)
                ldsm4(bq[2*j][0], bq[2*j][1], bq[2*j+1][0], bq[2*j+1][1],
                      Bb + ((wn*32 + j*16)*KST + ks*8)*4 + boff);
            #pragma unroll
            for (int mf = 0; mf < 4; mf++)
                #pragma unroll
                for (int nf = 0; nf < 4; nf++)
                    mma8(acc[mf][nf], a[mf], bq[nf]);
        }
    }
    __syncthreads();

    float* Cs = (float*)sq;
    #pragma unroll
    for (int mf = 0; mf < 4; mf++)
        #pragma unroll
        for (int nf = 0; nf < 4; nf++) {
            int row = wm*64 + mf*16 + g, col = wn*32 + nf*8 + 2*t;
            Cs[row*CST + col]       = acc[mf][nf][0];
            Cs[row*CST + col + 1]   = acc[mf][nf][1];
            Cs[(row+8)*CST + col]   = acc[mf][nf][2];
            Cs[(row+8)*CST + col+1] = acc[mf][nf][3];
        }
    __syncthreads();

    {   // LayerNorm over head_dim=64 (2 head-groups per 128-col tile)
        int row = tid >> 1, grp = tid & 1;
        const float* src = Cs + row*CST + grp*64;
        float sum = 0.f, sqs = 0.f;
        #pragma unroll
        for (int j = 0; j < 64; j++) { float x = src[j]; sum += x; sqs += x*x; }
        float mu = sum * (1.f/64.f);
        float var = sqs * (1.f/64.f) - mu*mu;
        float rs = rsqrtf(var + 1e-5f);
        int gm = mt*128 + row;
        int s = gm >> 12, b = (gm >> 10) & 3, n = gm & 1023;
        int tq = bn / CC;
        int h = ((bn % CC) >> 6) + grp;
        if (tq < 2) {
            float* dst = (tq == 0 ? g_q : g_k)
                       + ((((size_t)(s*BB+b)*HH + h)*NN + n)*HD);
            #pragma unroll
            for (int j = 0; j < 64; j += 4) {
                float4 o;
                o.x = f2tf((src[j+0]-mu)*rs*s_lng[j+0] + s_lnb[j+0]);
                o.y = f2tf((src[j+1]-mu)*rs*s_lng[j+1] + s_lnb[j+1]);
                o.z = f2tf((src[j+2]-mu)*rs*s_lng[j+2] + s_lnb[j+2]);
                o.w = f2tf((src[j+3]-mu)*rs*s_lng[j+3] + s_lnb[j+3]);
                *(float4*)(dst + j) = o;
            }
        } else {
            float* dstT = g_v + (((size_t)(s*BB+b)*HH + h)*HD)*NN + n;
            #pragma unroll
            for (int j = 0; j < 64; j++)
                dstT[(size_t)j*NN] = f2tf((src[j]-mu)*rs*s_lng[j] + s_lnb[j]);
        }
    }
}

// =====================================================================
// Kernel 2: attention. 256 thr = 8 warps, q-tile 128, 2 CTAs/SM.
// Q fragments hoisted to registers; K/V double-buffered via cp.async;
// V pre-transposed in global. smem = (2K + 2V + P) = 104448 B.
// =====================================================================
#define TST 68

__global__ __launch_bounds__(256, 2) void attn_mma() {
    extern __shared__ __align__(16) unsigned sa[];
    const unsigned KW0 = 0;              // 2 x 64*TST K buffers
    const unsigned VW0 = 2*64*TST;       // 2 x 64*TST Vt buffers
    const unsigned PW  = 4*64*TST;       // 128*TST (P; also Q staging)

    const int bx = blockIdx.x;
    const int qt = bx & 7;
    const int h  = (bx >> 3) % 12;
    const int b  = (bx / 96) & 3;
    const int p  = bx / 384;
    const int qs = 1 - p, kvs = p;

    const float* qptr  = g_q + (((size_t)(qs*BB+b)*HH + h)*NN + qt*128)*HD;
    const float* kptr  = g_k + (((size_t)(kvs*BB+b)*HH + h)*NN)*HD;
    const float* vptrT = g_v + (((size_t)(kvs*BB+b)*HH + h)*HD)*NN;   // [d][n]

    const int tid = threadIdx.x, w = tid >> 5, lane = tid & 31;
    const int g = lane >> 2, t = lane & 3;
    const unsigned smb = s2u(sa);

    const unsigned aoff = (((lane & 15)*TST + (lane >> 4)*4))*4;
    const unsigned boff = ((((((lane >> 4) << 3)) + (lane & 7))*TST + ((lane >> 3) & 1)*4))*4;
    const unsigned Pwb = smb + (PW + w*16*TST)*4;
    const unsigned Pwidx = PW + w*16*TST;

    // per-thread staging coords (4 cp16 for K, 4 for Vt)
    int srow[4], su4[4];
    #pragma unroll
    for (int i = 0; i < 4; i++) {
        int id = tid + i*256; srow[i] = id >> 4; su4[i] = (id & 15)*4;
    }

    // prefetch kc=0 into buffer 0 (K/V regions; independent of Q staging)
    #pragma unroll
    for (int i = 0; i < 4; i++) {
        cp16(smb + (KW0 + srow[i]*TST + su4[i])*4, kptr + srow[i]*64 + su4[i]);
        cp16(smb + (VW0 + srow[i]*TST + su4[i])*4, vptrT + (size_t)srow[i]*NN + su4[i]);
    }
    CPCOMMIT();

    // stage Q (128x64) through the P region, then hoist fragments to regs
    #pragma unroll
    for (int i = 0; i < 8; i++) {
        int id = tid + i*256, row = id >> 4, u4 = (id & 15)*4;
        *(float4*)&sa[PW + row*TST + u4] = *(const float4*)(qptr + row*64 + u4);
    }
    __syncthreads();
    unsigned q[8][4];
    #pragma unroll
    for (int ks = 0; ks < 8; ks++)
        ldsm4(q[ks][0], q[ks][1], q[ks][2], q[ks][3],
              smb + (PW + (w*16)*TST + ks*8)*4 + aoff);
    __syncwarp();   // q-frag reads done before this warp's P writes

    const float SC = 0.125f * 1.44269504088896f;   // scale * log2(e)
    float o[8][4] = {};
    float m0 = -1e30f, m1 = -1e30f, l0 = 0.f, l1 = 0.f;

    for (int kc = 0; kc < 16; kc++) {
        __syncthreads();                   // prev-iter reads of buf[(kc+1)&1] done
        if (kc < 15) {
            const float* kp = kptr + (kc+1)*64*64;
            const unsigned kb = smb + (KW0 + ((kc+1)&1)*64*TST)*4;
            const unsigned vb = smb + (VW0 + ((kc+1)&1)*64*TST)*4;
            #pragma unroll
            for (int i = 0; i < 4; i++) {
                cp16(kb + (srow[i]*TST + su4[i])*4, kp + srow[i]*64 + su4[i]);
                cp16(vb + (srow[i]*TST + su4[i])*4,
                     vptrT + (size_t)srow[i]*NN + (kc+1)*64 + su4[i]);
            }
            CPCOMMIT();
            asm volatile("cp.async.wait_group 1;");
        } else {
            asm volatile("cp.async.wait_group 0;");
        }
        __syncthreads();                   // buf[kc&1] visible

        const unsigned KWb = KW0 + (kc&1)*64*TST;
        const unsigned VWb = VW0 + (kc&1)*64*TST;

        // S = Q K^T  (Q from registers)
        float s[8][4] = {};
        #pragma unroll
        for (int ks = 0; ks < 8; ks++) {
            #pragma unroll
            for (int j = 0; j < 4; j++) {
                unsigned bf0[2], bf1[2];
                ldsm4(bf0[0], bf0[1], bf1[0], bf1[1],
                      smb + (KWb + (j*16)*TST + ks*8)*4 + boff);
                mma8(s[2*j], q[ks], bf0);
                mma8(s[2*j+1], q[ks], bf1);
            }
        }

        // online softmax in exp2 domain (warp-local; rows g and g+8)
        float mx0 = -1e30f, mx1 = -1e30f;
        #pragma unroll
        for (int nf = 0; nf < 8; nf++) {
            #pragma unroll
            for (int j = 0; j < 4; j++) s[nf][j] *= SC;
            mx0 = fmaxf(mx0, fmaxf(s[nf][0], s[nf][1]));
            mx1 = fmaxf(mx1, fmaxf(s[nf][2], s[nf][3]));
        }
        mx0 = fmaxf(mx0, __shfl_xor_sync(0xffffffffu, mx0, 1));
        mx0 = fmaxf(mx0, __shfl_xor_sync(0xffffffffu, mx0, 2));
        mx1 = fmaxf(mx1, __shfl_xor_sync(0xffffffffu, mx1, 1));
        mx1 = fmaxf(mx1, __shfl_xor_sync(0xffffffffu, mx1, 2));
        float M0 = fmaxf(m0, mx0), M1 = fmaxf(m1, mx1);
        float c0 = ex2f(m0 - M0), c1 = ex2f(m1 - M1);
        float ls0 = 0.f, ls1 = 0.f;
        #pragma unroll
        for (int nf = 0; nf < 8; nf++) {
            float p00 = ex2f(s[nf][0] - M0), p01 = ex2f(s[nf][1] - M0);
            float p10 = ex2f(s[nf][2] - M1), p11 = ex2f(s[nf][3] - M1);
            ls0 += p00 + p01; ls1 += p10 + p11;
            unsigned idx = Pwidx + g*TST + nf*8 + 2*t;
            sa[idx]           = f2t(p00); sa[idx + 1]         = f2t(p01);
            sa[idx + 8*TST]   = f2t(p10); sa[idx + 8*TST + 1] = f2t(p11);
        }
        ls0 += __shfl_xor_sync(0xffffffffu, ls0, 1);
        ls0 += __shfl_xor_sync(0xffffffffu, ls0, 2);
        ls1 += __shfl_xor_sync(0xffffffffu, ls1, 1);
        ls1 += __shfl_xor_sync(0xffffffffu, ls1, 2);
        l0 = l0*c0 + ls0; l1 = l1*c1 + ls1;
        m0 = M0; m1 = M1;
        #pragma unroll
        for (int nf = 0; nf < 8; nf++) {
            o[nf][0] *= c0; o[nf][1] *= c0; o[nf][2] *= c1; o[nf][3] *= c1;
        }
        __syncwarp();   // P visible within warp

        // O += P @ V
        #pragma unroll
        for (int ks = 0; ks < 8; ks++) {
            unsigned a[4];
            ldsm4(a[0], a[1], a[2], a[3], Pwb + (ks*8)*4 + aoff);
            #pragma unroll
            for (int j = 0; j < 4; j++) {
                unsigned bf0[2], bf1[2];
                ldsm4(bf0[0], bf0[1], bf1[0], bf1[1],
                      smb + (VWb + (j*16)*TST + ks*8)*4 + boff);
                mma8(o[2*j], a, bf0);
                mma8(o[2*j+1], a, bf1);
            }
        }
    }

    const int qrow = qt*128 + w*16;
    float inv0 = 1.f / l0, inv1 = 1.f / l1;
    float* op = g_ctx + (((size_t)(p*BB+b)*HH + h)*NN + qrow)*HD;
    #pragma unroll
    for (int nf = 0; nf < 8; nf++) {
        *(float2*)(op + g*64 + nf*8 + 2*t) =
            make_float2(f2tf(o[nf][0]*inv0), f2tf(o[nf][1]*inv0));
        *(float2*)(op + (g+8)*64 + nf*8 + 2*t) =
            make_float2(f2tf(o[nf][2]*inv1), f2tf(o[nf][3]*inv1));
    }
}

// =====================================================================
// Kernel 3: projection GEMM (3-stage, 1 sync/iter) + bias + q-residual.
// =====================================================================
__global__ __launch_bounds__(256, 2) void proj_gemm_mma(
    const float* __restrict__ bias, float* __restrict__ out)
{
    extern __shared__ __align__(16) unsigned sp[];
    const int tid = threadIdx.x;
    const int warp = tid >> 5, lane = tid & 31;
    const int wm = warp >> 2, wn = warp & 3;
    const int g = lane >> 2, t = lane & 3;
    const int mt = blockIdx.y;
    const int bn = blockIdx.x * 128;
    const unsigned smb = s2u(sp);

    const float* abase[4]; int au[4]; unsigned adst[4];
    const float* bsrc[4]; unsigned bdst[4];
    #pragma unroll
    for (int i = 0; i < 4; i++) {
        int c = tid + i*256, row = c >> 3, u4 = (c & 7) * 4;
        int gm = mt*128 + row;
        int pp = gm >> 12, b2 = (gm >> 10) & 3, n = gm & 1023;
        abase[i] = g_ctx + (size_t)(pp*BB + b2)*PERSB + (size_t)n*HD;
        au[i] = u4;
        adst[i] = smb + (row*KST + u4)*4;
        bsrc[i] = g_wp + (size_t)(bn + row)*CC + u4;
        bdst[i] = smb + (ABUFW + row*KST + u4)*4;
    }
    const unsigned aoff = AOFF_G(lane);
    const unsigned boff = BOFF_G(lane);

    float acc[4][4][4] = {};

    #pragma unroll
    for (int i = 0; i < 4; i++) {
        cp16(adst[i], abase[i] + (au[i] >> 6)*(NN*HD) + (au[i] & 63));
        cp16(bdst[i], bsrc[i]);
    }
    CPCOMMIT();
    #pragma unroll
    for (int i = 0; i < 4; i++) {
        int k = 32 + au[i];
        cp16(adst[i]+BUFB, abase[i] + (k >> 6)*(NN*HD) + (k & 63));
        cp16(bdst[i]+BUFB, bsrc[i] + 32);
    }
    CPCOMMIT();

    unsigned rdo = 0, wro = 2*BUFB;
    for (int kt = 0; kt < 24; kt++) {
        if (kt < 23) { asm volatile("cp.async.wait_group 1;"); }
        else         { asm volatile("cp.async.wait_group 0;"); }
        __syncthreads();
        if (kt < 22) {
            #pragma unroll
            for (int i = 0; i < 4; i++) {
                int k = (kt+2)*32 + au[i];
                cp16(adst[i] + wro, abase[i] + (k >> 6)*(NN*HD) + (k & 63));
                cp16(bdst[i] + wro, bsrc[i] + (kt+2)*32);
            }
            CPCOMMIT();
            wro += BUFB; if (wro == 3*BUFB) wro = 0;
        }
        const unsigned Ab = smb + rdo;
        const unsigned Bb = Ab + ABUFW*4;
        rdo += BUFB; if (rdo == 3*BUFB) rdo = 0;
        #pragma unroll
        for (int ks = 0; ks < 4; ks++) {
            unsigned a[4][4], bq[4][2];
            #pragma unroll
            for (int mf = 0; mf < 4; mf++)
                ldsm4(a[mf][0], a[mf][1], a[mf][2], a[mf][3],
                      Ab + ((wm*64 + mf*16)*KST + ks*8)*4 + aoff);
            #pragma unroll
            for (int j = 0; j < 2; j++)
                ldsm4(bq[2*j][0], bq[2*j][1], bq[2*j+1][0], bq[2*j+1][1],
                      Bb + ((wn*32 + j*16)*KST + ks*8)*4 + boff);
            #pragma unroll
            for (int mf = 0; mf < 4; mf++)
                #pragma unroll
                for (int nf = 0; nf < 4; nf++)
                    mma8(acc[mf][nf], a[mf], bq[nf]);
        }
    }

    // epilogue: bias + flat-q residual -> d_out
    #pragma unroll
    for (int mf = 0; mf < 4; mf++) {
        #pragma unroll
        for (int rr = 0; rr < 2; rr++) {
            int gm = mt*128 + wm*64 + mf*16 + g + rr*8;
            int pp = gm >> 12, b2 = (gm >> 10) & 3, n = gm & 1023;
            const float* qres = g_q + (size_t)((1-pp)*BB + b2)*PERSB + (size_t)n*CC;
            #pragma unroll
            for (int nf = 0; nf < 4; nf++) {
                int col = bn + wn*32 + nf*8 + 2*t;
                float2 r;
                r.x = acc[mf][nf][2*rr+0] + __ldg(bias + col)   + __ldg(qres + col);
                r.y = acc[mf][nf][2*rr+1] + __ldg(bias + col+1) + __ldg(qres + col+1);
                *(float2*)(out + (size_t)gm*CC + col) = r;
            }
        }
    }
}

// =====================================================================
extern "C" void kernel_launch(void* const* d_in, const int* in_sizes, int n_in,
                              void* d_out, int out_size) {
    const float* before = (const float*)d_in[0];
    const float* after  = (const float*)d_in[1];
    const float* W_qkv  = (const float*)d_in[2];
    const float* ln_g   = (const float*)d_in[3];
    const float* ln_b   = (const float*)d_in[4];
    const float* W_proj = (const float*)d_in[5];
    const float* b_proj = (const float*)d_in[6];
    float* out = (float*)d_out;

    const int gemm_smem = 3 * BUFB;                    // 110592 B
    const int attn_smem = 384 * TST * 4;               // 104448 B (2 CTAs/SM)

    // 0) pre-round inputs to tf32
    preround_kernel<<<PRTOT/256, 256>>>(before, after, W_qkv, W_proj);

    // 1) QKV GEMM + fused LN
    {
        cudaFuncSetAttribute(qkv_gemm_mma, cudaFuncAttributeMaxDynamicSharedMemorySize, gemm_smem);
        dim3 grid(QKV3/128, MROWS/128);
        qkv_gemm_mma<<<grid, 256, gemm_smem>>>(ln_g, ln_b);
    }
    // 2) Attention: 768 blocks
    {
        cudaFuncSetAttribute(attn_mma, cudaFuncAttributeMaxDynamicSharedMemorySize, attn_smem);
        attn_mma<<<768, 256, attn_smem>>>();
    }
    // 3) Projection GEMM
    {
        cudaFuncSetAttribute(proj_gemm_mma, cudaFuncAttributeMaxDynamicSharedMemorySize, gemm_smem);
        dim3 grid(CC/128, MROWS/128);
        proj_gemm_mma<<<grid, 256, gemm_smem>>>(b_proj, out);
    }
}

// round 9
// speedup vs baseline: 2.6990x; 1.5820x over previous
#include <cuda_runtime.h>
#include <cuda_fp16.h>
#include <math.h>

#define BB 4
#define NN 1024
#define CC 768
#define HH 12
#define HD 64
#define QKV3 (3*CC)          // 2304
#define MROWS (2*BB*NN)      // 8192
#define PERSB (HH*NN*HD)     // 786432 elems per (stream,b)

// -------- scratch (device globals; no allocation) --------
__device__ __half g_q  [2*BB*HH*NN*HD];   // [s][b][h][n][d]
__device__ __half g_k  [2*BB*HH*NN*HD];   // [s][b][h][n][d]
__device__ __half g_v  [2*BB*HH*NN*HD];   // [s][b][h][n][d] (natural again)
__device__ __half g_ctx[2*BB*HH*NN*HD];   // [p][b][h][n][d]
__device__ __half g_x  [MROWS*CC];        // fp16 [before;after]
__device__ __half g_wq [QKV3*CC];         // fp16 W_qkv
__device__ __half g_wp [CC*CC];           // fp16 W_proj

// -------- helpers --------
__device__ __forceinline__ float ex2f(float x) {
    float y; asm("ex2.approx.ftz.f32 %0, %1;" : "=f"(y) : "f"(x)); return y;
}
__device__ __forceinline__ unsigned pack2(float lo, float hi) {
    unsigned r; asm("cvt.rn.f16x2.f32 %0, %1, %2;" : "=r"(r) : "f"(hi), "f"(lo));
    return r;
}
__device__ __forceinline__ void mma16(float* c, const unsigned* a, const unsigned* b) {
    asm volatile("mma.sync.aligned.m16n8k16.row.col.f32.f16.f16.f32 "
        "{%0,%1,%2,%3}, {%4,%5,%6,%7}, {%8,%9}, {%0,%1,%2,%3};"
        : "+f"(c[0]), "+f"(c[1]), "+f"(c[2]), "+f"(c[3])
        : "r"(a[0]), "r"(a[1]), "r"(a[2]), "r"(a[3]), "r"(b[0]), "r"(b[1]));
}
__device__ __forceinline__ void ldsm4(unsigned& r0, unsigned& r1, unsigned& r2,
                                      unsigned& r3, unsigned addr) {
    asm volatile("ldmatrix.sync.aligned.m8n8.x4.shared.b16 {%0,%1,%2,%3}, [%4];"
        : "=r"(r0), "=r"(r1), "=r"(r2), "=r"(r3) : "r"(addr));
}
__device__ __forceinline__ void ldsm4t(unsigned& r0, unsigned& r1, unsigned& r2,
                                       unsigned& r3, unsigned addr) {
    asm volatile("ldmatrix.sync.aligned.m8n8.x4.trans.shared.b16 {%0,%1,%2,%3}, [%4];"
        : "=r"(r0), "=r"(r1), "=r"(r2), "=r"(r3) : "r"(addr));
}
__device__ __forceinline__ unsigned s2u(const void* p) {
    return (unsigned)__cvta_generic_to_shared(p);
}
__device__ __forceinline__ void cp16(unsigned dst, const void* src) {
    asm volatile("cp.async.cg.shared.global [%0], [%1], 16;" :: "r"(dst), "l"(src));
}
#define CPCOMMIT() asm volatile("cp.async.commit_group;")

// GEMM tiling: 128x128 block, K-step 32 (2 x k16 chunks), 8 warps (2x4), 3-stage.
// fp16 row stride: 32 k + 8 pad = 40 halves = 80 bytes (5x16B -> LDSM conflict-free)
#define GRS   80              // bytes per staged row
#define GTILE (128*GRS)       // 10240 B per operand tile
#define GSTGB (2*GTILE)       // 20480 B per stage (A + B)
#define CST   133             // qkv epilogue C stride (floats)

// ldmatrix lane->offset maps (byte offsets within a tile)
#define AOFFG(lane) (((lane)&15)*GRS + ((lane)>>4)*16)
#define BOFFG(lane) ((((lane)&7) + (((lane)>>4)&1)*8)*GRS + (((lane)>>3)&1)*16)

// =====================================================================
// Kernel 0: convert inputs to fp16 (once). 8 floats per thread.
// =====================================================================
#define XQ8 (MROWS*CC/8)     // 786432
#define WQ8 (QKV3*CC/8)      // 221184
#define PQ8 (CC*CC/8)        // 73728
#define PR8 (XQ8+WQ8+PQ8)    // 1081344 = 4224*256

__global__ __launch_bounds__(256) void preround_kernel(
    const float* __restrict__ before, const float* __restrict__ after,
    const float* __restrict__ Wqkv, const float* __restrict__ Wp)
{
    int i = blockIdx.x*256 + threadIdx.x;
    const float* src; __half* dst;
    if (i < XQ8) {
        src = (i < XQ8/2) ? before + (size_t)i*8 : after + (size_t)(i - XQ8/2)*8;
        dst = g_x + (size_t)i*8;
    } else if (i < XQ8 + WQ8) {
        src = Wqkv + (size_t)(i - XQ8)*8;
        dst = g_wq + (size_t)(i - XQ8)*8;
    } else {
        src = Wp + (size_t)(i - XQ8 - WQ8)*8;
        dst = g_wp + (size_t)(i - XQ8 - WQ8)*8;
    }
    float4 v0 = ((const float4*)src)[0];
    float4 v1 = ((const float4*)src)[1];
    uint4 o;
    o.x = pack2(v0.x, v0.y); o.y = pack2(v0.z, v0.w);
    o.z = pack2(v1.x, v1.y); o.w = pack2(v1.z, v1.w);
    *(uint4*)dst = o;
}

// =====================================================================
// Kernel 1: QKV GEMM (fp16 m16n8k16, 3-stage cp.async) + fused LN.
// =====================================================================
__global__ __launch_bounds__(256, 2) void qkv_gemm_mma(
    const float* __restrict__ ln_g, const float* __restrict__ ln_b)
{
    extern __shared__ __align__(16) unsigned char sq[];
    __shared__ float s_lng[64], s_lnb[64];
    const int tid = threadIdx.x;
    if (tid < 64) { s_lng[tid] = ln_g[tid]; s_lnb[tid] = ln_b[tid]; }

    const int warp = tid >> 5, lane = tid & 31;
    const int wm = warp >> 2, wn = warp & 3;
    const int g = lane >> 2, t = lane & 3;
    const int mt = blockIdx.y;
    const int bn = blockIdx.x * 128;
    const unsigned smb = s2u(sq);

    // staging: per thread 2 A-chunks + 2 B-chunks (16B each) per stage
    const __half* asr[2]; unsigned ad[2];
    const __half* bsr[2]; unsigned bd[2];
    #pragma unroll
    for (int i = 0; i < 2; i++) {
        int id = tid + i*256, r = id >> 2, ch = id & 3;
        asr[i] = g_x + (size_t)(mt*128 + r)*CC + ch*8;
        ad[i]  = smb + r*GRS + ch*16;
        bsr[i] = g_wq + (size_t)(bn + r)*CC + ch*8;
        bd[i]  = smb + GTILE + r*GRS + ch*16;
    }
    const unsigned aoff = AOFFG(lane);
    const unsigned boff = BOFFG(lane);

    float acc[4][4][4] = {};

    #pragma unroll
    for (int i = 0; i < 2; i++) { cp16(ad[i], asr[i]); cp16(bd[i], bsr[i]); }
    CPCOMMIT();
    #pragma unroll
    for (int i = 0; i < 2; i++) { cp16(ad[i]+GSTGB, asr[i]+32); cp16(bd[i]+GSTGB, bsr[i]+32); }
    CPCOMMIT();

    unsigned rdo = 0, wro = 2*GSTGB;
    for (int kt = 0; kt < 24; kt++) {
        if (kt < 23) { asm volatile("cp.async.wait_group 1;"); }
        else         { asm volatile("cp.async.wait_group 0;"); }
        __syncthreads();
        if (kt < 22) {
            #pragma unroll
            for (int i = 0; i < 2; i++) {
                cp16(ad[i] + wro, asr[i] + (kt+2)*32);
                cp16(bd[i] + wro, bsr[i] + (kt+2)*32);
            }
            CPCOMMIT();
            wro += GSTGB; if (wro == 3*GSTGB) wro = 0;
        }
        const unsigned Ab = smb + rdo;
        const unsigned Bb = Ab + GTILE;
        rdo += GSTGB; if (rdo == 3*GSTGB) rdo = 0;
        #pragma unroll
        for (int kk = 0; kk < 2; kk++) {
            unsigned a[4][4], bq[4][2];
            #pragma unroll
            for (int mf = 0; mf < 4; mf++)
                ldsm4(a[mf][0], a[mf][1], a[mf][2], a[mf][3],
                      Ab + (wm*64 + mf*16)*GRS + kk*32 + aoff);
            #pragma unroll
            for (int g2 = 0; g2 < 2; g2++) {
                unsigned r0, r1, r2, r3;
                ldsm4(r0, r1, r2, r3, Bb + (wn*32 + g2*16)*GRS + kk*32 + boff);
                bq[2*g2][0] = r0; bq[2*g2][1] = r1;
                bq[2*g2+1][0] = r2; bq[2*g2+1][1] = r3;
            }
            #pragma unroll
            for (int mf = 0; mf < 4; mf++)
                #pragma unroll
                for (int nf = 0; nf < 4; nf++)
                    mma16(acc[mf][nf], a[mf], bq[nf]);
        }
    }
    __syncthreads();   // all warps done before Cs aliases the staging buffers

    float* Cs = (float*)sq;
    #pragma unroll
    for (int mf = 0; mf < 4; mf++)
        #pragma unroll
        for (int nf = 0; nf < 4; nf++) {
            int row = wm*64 + mf*16 + g, col = wn*32 + nf*8 + 2*t;
            Cs[row*CST + col]       = acc[mf][nf][0];
            Cs[row*CST + col + 1]   = acc[mf][nf][1];
            Cs[(row+8)*CST + col]   = acc[mf][nf][2];
            Cs[(row+8)*CST + col+1] = acc[mf][nf][3];
        }
    __syncthreads();

    {   // LayerNorm over head_dim=64 (2 head-groups per 128-col tile), fp16 out
        int row = tid >> 1, grp = tid & 1;
        const float* src = Cs + row*CST + grp*64;
        float sum = 0.f, sqs = 0.f;
        #pragma unroll
        for (int j = 0; j < 64; j++) { float x = src[j]; sum += x; sqs += x*x; }
        float mu = sum * (1.f/64.f);
        float var = sqs * (1.f/64.f) - mu*mu;
        float rs = rsqrtf(var + 1e-5f);
        int gm = mt*128 + row;
        int s = gm >> 12, b = (gm >> 10) & 3, n = gm & 1023;
        int tq = bn / CC;                       // 0=q,1=k,2=v (tile never straddles)
        int h = ((bn % CC) >> 6) + grp;
        __half* dst = (tq == 0 ? g_q : tq == 1 ? g_k : g_v)
                    + ((((size_t)(s*BB+b)*HH + h)*NN + n)*HD);
        #pragma unroll
        for (int j = 0; j < 64; j += 2) {
            float v0 = (src[j+0]-mu)*rs*s_lng[j+0] + s_lnb[j+0];
            float v1 = (src[j+1]-mu)*rs*s_lng[j+1] + s_lnb[j+1];
            *(__half2*)(dst + j) = __floats2half2_rn(v0, v1);
        }
    }
}

// =====================================================================
// Kernel 2: attention, fp16 m16n8k16. 256 thr = 8 warps, q-tile 128,
// 2 CTAs/SM. Q hoisted to regs; P packed straight from accumulators
// (NO smem round trip); K/V double-buffered cp.async; V natural layout.
// smem: Q 18432 + 2xK 18432 + 2xV 18432 = 55296 B.
// =====================================================================
#define ARS 144               // attention staged row: 64 halves + 8 pad = 144 B
#define QB  0
#define KB0 (128*ARS)         // 18432
#define VB0 (KB0 + 2*64*ARS)  // 36864
#define ATTN_SMEM (VB0 + 2*64*ARS)   // 55296

__global__ __launch_bounds__(256, 2) void attn_mma() {
    extern __shared__ __align__(16) unsigned char sa[];
    const unsigned smb = s2u(sa);

    const int bx = blockIdx.x;
    const int qt = bx & 7;
    const int h  = (bx >> 3) % 12;
    const int b  = (bx / 96) & 3;
    const int p  = bx / 384;
    const int qs = 1 - p, kvs = p;

    const __half* qptr = g_q + (((size_t)(qs*BB+b)*HH + h)*NN + qt*128)*HD;
    const __half* kptr = g_k + (((size_t)(kvs*BB+b)*HH + h)*NN)*HD;
    const __half* vptr = g_v + (((size_t)(kvs*BB+b)*HH + h)*NN)*HD;

    const int tid = threadIdx.x, w = tid >> 5, lane = tid & 31;
    const int g = lane >> 2, t = lane & 3;

    const unsigned aoffA = ((lane & 15)*ARS + (lane >> 4)*16);
    const unsigned boffK = (((lane & 7) + ((lane >> 4) & 1)*8)*ARS + ((lane >> 3) & 1)*16);
    const unsigned boffV = (((lane & 7) + ((lane >> 3) & 1)*8)*ARS + (lane >> 4)*16);

    // K/V staging coords: 64 rows x 8 chunks each; 2 K + 2 V cp16 per thread
    int srow[2], sch[2];
    #pragma unroll
    for (int i = 0; i < 2; i++) {
        int id = tid + i*256; srow[i] = id >> 3; sch[i] = id & 7;
    }

    // prefetch kc=0 into buffer 0
    #pragma unroll
    for (int i = 0; i < 2; i++) {
        cp16(smb + KB0 + srow[i]*ARS + sch[i]*16, kptr + srow[i]*64 + sch[i]*8);
        cp16(smb + VB0 + srow[i]*ARS + sch[i]*16, vptr + srow[i]*64 + sch[i]*8);
    }
    CPCOMMIT();

    // stage Q (128x64 fp16) and hoist fragments to registers
    #pragma unroll
    for (int i = 0; i < 4; i++) {
        int id = tid + i*256, row = id >> 3, ch = id & 7;
        *(uint4*)(sa + QB + row*ARS + ch*16) = *(const uint4*)(qptr + row*64 + ch*8);
    }
    __syncthreads();
    unsigned q[4][4];
    #pragma unroll
    for (int kk = 0; kk < 4; kk++)
        ldsm4(q[kk][0], q[kk][1], q[kk][2], q[kk][3],
              smb + QB + (w*16)*ARS + kk*32 + aoffA);

    const float SC = 0.125f * 1.44269504088896f;   // scale * log2(e)
    float o[8][4] = {};
    float m0 = -1e30f, m1 = -1e30f, l0 = 0.f, l1 = 0.f;

    for (int kc = 0; kc < 16; kc++) {
        __syncthreads();                   // prev-iter reads of buf[(kc+1)&1] done
        if (kc < 15) {
            const __half* kp = kptr + (kc+1)*64*64;
            const __half* vp = vptr + (kc+1)*64*64;
            const unsigned kb = smb + KB0 + ((kc+1)&1)*(64*ARS);
            const unsigned vb = smb + VB0 + ((kc+1)&1)*(64*ARS);
            #pragma unroll
            for (int i = 0; i < 2; i++) {
                cp16(kb + srow[i]*ARS + sch[i]*16, kp + srow[i]*64 + sch[i]*8);
                cp16(vb + srow[i]*ARS + sch[i]*16, vp + srow[i]*64 + sch[i]*8);
            }
            CPCOMMIT();
            asm volatile("cp.async.wait_group 1;");
        } else {
            asm volatile("cp.async.wait_group 0;");
        }
        __syncthreads();                   // buf[kc&1] visible

        const unsigned Kb = smb + KB0 + (kc&1)*(64*ARS);
        const unsigned Vb = smb + VB0 + (kc&1)*(64*ARS);

        // S = Q K^T : 4 d-chunks x 4 kv-group-pairs
        float s[8][4] = {};
        #pragma unroll
        for (int kk = 0; kk < 4; kk++) {
            #pragma unroll
            for (int j2 = 0; j2 < 4; j2++) {
                unsigned r0, r1, r2, r3;
                ldsm4(r0, r1, r2, r3, Kb + (j2*16)*ARS + kk*32 + boffK);
                unsigned bf0[2] = {r0, r1}, bf1[2] = {r2, r3};
                mma16(s[2*j2], q[kk], bf0);
                mma16(s[2*j2+1], q[kk], bf1);
            }
        }

        // online softmax (warp-local; rows g and g+8), P stays in registers
        float mx0 = -1e30f, mx1 = -1e30f;
        #pragma unroll
        for (int nf = 0; nf < 8; nf++) {
            #pragma unroll
            for (int j = 0; j < 4; j++) s[nf][j] *= SC;
            mx0 = fmaxf(mx0, fmaxf(s[nf][0], s[nf][1]));
            mx1 = fmaxf(mx1, fmaxf(s[nf][2], s[nf][3]));
        }
        mx0 = fmaxf(mx0, __shfl_xor_sync(0xffffffffu, mx0, 1));
        mx0 = fmaxf(mx0, __shfl_xor_sync(0xffffffffu, mx0, 2));
        mx1 = fmaxf(mx1, __shfl_xor_sync(0xffffffffu, mx1, 1));
        mx1 = fmaxf(mx1, __shfl_xor_sync(0xffffffffu, mx1, 2));
        float M0 = fmaxf(m0, mx0), M1 = fmaxf(m1, mx1);
        float c0 = ex2f(m0 - M0), c1 = ex2f(m1 - M1);
        float ls0 = 0.f, ls1 = 0.f;
        #pragma unroll
        for (int nf = 0; nf < 8; nf++) {
            s[nf][0] = ex2f(s[nf][0] - M0);
            s[nf][1] = ex2f(s[nf][1] - M0);
            s[nf][2] = ex2f(s[nf][2] - M1);
            s[nf][3] = ex2f(s[nf][3] - M1);
            ls0 += s[nf][0] + s[nf][1];
            ls1 += s[nf][2] + s[nf][3];
        }
        ls0 += __shfl_xor_sync(0xffffffffu, ls0, 1);
        ls0 += __shfl_xor_sync(0xffffffffu, ls0, 2);
        ls1 += __shfl_xor_sync(0xffffffffu, ls1, 1);
        ls1 += __shfl_xor_sync(0xffffffffu, ls1, 2);
        l0 = l0*c0 + ls0; l1 = l1*c1 + ls1;
        m0 = M0; m1 = M1;
        #pragma unroll
        for (int nf = 0; nf < 8; nf++) {
            o[nf][0] *= c0; o[nf][1] *= c0; o[nf][2] *= c1; o[nf][3] *= c1;
        }

        // O += P @ V : P packed from accumulators, V via ldmatrix.trans
        #pragma unroll
        for (int kc2 = 0; kc2 < 4; kc2++) {
            unsigned a[4];
            a[0] = pack2(s[2*kc2][0],   s[2*kc2][1]);
            a[1] = pack2(s[2*kc2][2],   s[2*kc2][3]);
            a[2] = pack2(s[2*kc2+1][0], s[2*kc2+1][1]);
            a[3] = pack2(s[2*kc2+1][2], s[2*kc2+1][3]);
            #pragma unroll
            for (int j = 0; j < 4; j++) {
                unsigned r0, r1, r2, r3;
                ldsm4t(r0, r1, r2, r3, Vb + (kc2*16)*ARS + j*32 + boffV);
                unsigned bf0[2] = {r0, r1}, bf1[2] = {r2, r3};
                mma16(o[2*j], a, bf0);
                mma16(o[2*j+1], a, bf1);
            }
        }
    }

    const int qrow = qt*128 + w*16;
    float inv0 = 1.f / l0, inv1 = 1.f / l1;
    __half* op = g_ctx + (((size_t)(p*BB+b)*HH + h)*NN + qrow)*HD;
    #pragma unroll
    for (int nf = 0; nf < 8; nf++) {
        *(__half2*)(op + g*64 + nf*8 + 2*t) =
            __floats2half2_rn(o[nf][0]*inv0, o[nf][1]*inv0);
        *(__half2*)(op + (g+8)*64 + nf*8 + 2*t) =
            __floats2half2_rn(o[nf][2]*inv1, o[nf][3]*inv1);
    }
}

// =====================================================================
// Kernel 3: projection GEMM (fp16, 3-stage) + bias + q-residual -> f32 out.
// =====================================================================
__global__ __launch_bounds__(256, 2) void proj_gemm_mma(
    const float* __restrict__ bias, float* __restrict__ out)
{
    extern __shared__ __align__(16) unsigned char sp[];
    const int tid = threadIdx.x;
    const int warp = tid >> 5, lane = tid & 31;
    const int wm = warp >> 2, wn = warp & 3;
    const int g = lane >> 2, t = lane & 3;
    const int mt = blockIdx.y;
    const int bn = blockIdx.x * 128;
    const unsigned smb = s2u(sp);

    const __half* actx[2]; unsigned ad[2];
    const __half* bsr[2]; unsigned bd[2];
    #pragma unroll
    for (int i = 0; i < 2; i++) {
        int id = tid + i*256, r = id >> 2, ch = id & 3;
        int gm = mt*128 + r;
        int pp = gm >> 12, b2 = (gm >> 10) & 3, n = gm & 1023;
        actx[i] = g_ctx + (size_t)(pp*BB + b2)*PERSB + (size_t)n*HD + ch*8;
        ad[i]   = smb + r*GRS + ch*16;
        bsr[i]  = g_wp + (size_t)(bn + r)*CC + ch*8;
        bd[i]   = smb + GTILE + r*GRS + ch*16;
    }
    const unsigned aoff = AOFFG(lane);
    const unsigned boff = BOFFG(lane);

    float acc[4][4][4] = {};

    #pragma unroll
    for (int i = 0; i < 2; i++) { cp16(ad[i], actx[i]); cp16(bd[i], bsr[i]); }
    CPCOMMIT();
    #pragma unroll
    for (int i = 0; i < 2; i++) {
        cp16(ad[i]+GSTGB, actx[i] + 32);          // chunk 1: head 0, d-half 1
        cp16(bd[i]+GSTGB, bsr[i] + 32);
    }
    CPCOMMIT();

    unsigned rdo = 0, wro = 2*GSTGB;
    for (int kt = 0; kt < 24; kt++) {
        if (kt < 23) { asm volatile("cp.async.wait_group 1;"); }
        else         { asm volatile("cp.async.wait_group 0;"); }
        __syncthreads();
        if (kt < 22) {
            int c = kt + 2;
            #pragma unroll
            for (int i = 0; i < 2; i++) {
                cp16(ad[i] + wro, actx[i] + (c >> 1)*(NN*HD) + (c & 1)*32);
                cp16(bd[i] + wro, bsr[i] + c*32);
            }
            CPCOMMIT();
            wro += GSTGB; if (wro == 3*GSTGB) wro = 0;
        }
        const unsigned Ab = smb + rdo;
        const unsigned Bb = Ab + GTILE;
        rdo += GSTGB; if (rdo == 3*GSTGB) rdo = 0;
        #pragma unroll
        for (int kk = 0; kk < 2; kk++) {
            unsigned a[4][4], bq[4][2];
            #pragma unroll
            for (int mf = 0; mf < 4; mf++)
                ldsm4(a[mf][0], a[mf][1], a[mf][2], a[mf][3],
                      Ab + (wm*64 + mf*16)*GRS + kk*32 + aoff);
            #pragma unroll
            for (int g2 = 0; g2 < 2; g2++) {
                unsigned r0, r1, r2, r3;
                ldsm4(r0, r1, r2, r3, Bb + (wn*32 + g2*16)*GRS + kk*32 + boff);
                bq[2*g2][0] = r0; bq[2*g2][1] = r1;
                bq[2*g2+1][0] = r2; bq[2*g2+1][1] = r3;
            }
            #pragma unroll
            for (int mf = 0; mf < 4; mf++)
                #pragma unroll
                for (int nf = 0; nf < 4; nf++)
                    mma16(acc[mf][nf], a[mf], bq[nf]);
        }
    }

    // epilogue: bias + fp16 flat-q residual -> f32 d_out
    #pragma unroll
    for (int mf = 0; mf < 4; mf++) {
        #pragma unroll
        for (int rr = 0; rr < 2; rr++) {
            int gm = mt*128 + wm*64 + mf*16 + g + rr*8;
            int pp = gm >> 12, b2 = (gm >> 10) & 3, n = gm & 1023;
            const __half* qres = g_q + (size_t)((1-pp)*BB + b2)*PERSB + (size_t)n*CC;
            #pragma unroll
            for (int nf = 0; nf < 4; nf++) {
                int col = bn + wn*32 + nf*8 + 2*t;
                float2 qr = __half22float2(*(const __half2*)(qres + col));
                float2 r;
                r.x = acc[mf][nf][2*rr+0] + __ldg(bias + col)   + qr.x;
                r.y = acc[mf][nf][2*rr+1] + __ldg(bias + col+1) + qr.y;
                *(float2*)(out + (size_t)gm*CC + col) = r;
            }
        }
    }
}

// =====================================================================
extern "C" void kernel_launch(void* const* d_in, const int* in_sizes, int n_in,
                              void* d_out, int out_size) {
    const float* before = (const float*)d_in[0];
    const float* after  = (const float*)d_in[1];
    const float* W_qkv  = (const float*)d_in[2];
    const float* ln_g   = (const float*)d_in[3];
    const float* ln_b   = (const float*)d_in[4];
    const float* W_proj = (const float*)d_in[5];
    const float* b_proj = (const float*)d_in[6];
    float* out = (float*)d_out;

    const int qkv_smem  = 128*CST*4;          // 68096 (Cs; > 3*GSTGB staging)
    const int proj_smem = 3*GSTGB;            // 61440
    const int attn_smem = ATTN_SMEM;          // 55296

    // 0) convert inputs to fp16
    preround_kernel<<<PR8/256, 256>>>(before, after, W_qkv, W_proj);

    // 1) QKV GEMM + fused LN: grid (2304/128, 8192/128)
    {
        cudaFuncSetAttribute(qkv_gemm_mma, cudaFuncAttributeMaxDynamicSharedMemorySize, qkv_smem);
        dim3 grid(QKV3/128, MROWS/128);
        qkv_gemm_mma<<<grid, 256, qkv_smem>>>(ln_g, ln_b);
    }
    // 2) Attention: 768 blocks
    {
        cudaFuncSetAttribute(attn_mma, cudaFuncAttributeMaxDynamicSharedMemorySize, attn_smem);
        attn_mma<<<768, 256, attn_smem>>>();
    }
    // 3) Projection GEMM: grid (768/128, 8192/128)
    {
        cudaFuncSetAttribute(proj_gemm_mma, cudaFuncAttributeMaxDynamicSharedMemorySize, proj_smem);
        dim3 grid(CC/128, MROWS/128);
        proj_gemm_mma<<<grid, 256, proj_smem>>>(b_proj, out);
    }
}

// round 10
// speedup vs baseline: 3.0017x; 1.1122x over previous
#include <cuda_runtime.h>
#include <cuda_fp16.h>
#include <math.h>

#define BB 4
#define NN 1024
#define CC 768
#define HH 12
#define HD 64
#define QKV3 (3*CC)          // 2304
#define MROWS (2*BB*NN)      // 8192
#define PERSB (HH*NN*HD)     // 786432 elems per (stream,b)

// -------- scratch (device globals; no allocation) --------
__device__ __half g_q  [2*BB*HH*NN*HD];   // [s][b][h][n][d]
__device__ __half g_k  [2*BB*HH*NN*HD];   // [s][b][h][n][d]
__device__ __half g_v  [2*BB*HH*NN*HD];   // [s][b][h][n][d]
__device__ __half g_ctx[2*BB*HH*NN*HD];   // [p][b][h][n][d]
__device__ __half g_x  [MROWS*CC];        // fp16 [before;after]
__device__ __half g_wq [QKV3*CC];         // fp16 W_qkv
__device__ __half g_wp [CC*CC];           // fp16 W_proj

// -------- helpers --------
__device__ __forceinline__ float ex2f(float x) {
    float y; asm("ex2.approx.ftz.f32 %0, %1;" : "=f"(y) : "f"(x)); return y;
}
__device__ __forceinline__ unsigned pack2(float lo, float hi) {
    unsigned r; asm("cvt.rn.f16x2.f32 %0, %1, %2;" : "=r"(r) : "f"(hi), "f"(lo));
    return r;
}
__device__ __forceinline__ void mma16(float* c, const unsigned* a, const unsigned* b) {
    asm volatile("mma.sync.aligned.m16n8k16.row.col.f32.f16.f16.f32 "
        "{%0,%1,%2,%3}, {%4,%5,%6,%7}, {%8,%9}, {%0,%1,%2,%3};"
        : "+f"(c[0]), "+f"(c[1]), "+f"(c[2]), "+f"(c[3])
        : "r"(a[0]), "r"(a[1]), "r"(a[2]), "r"(a[3]), "r"(b[0]), "r"(b[1]));
}
__device__ __forceinline__ void ldsm4(unsigned& r0, unsigned& r1, unsigned& r2,
                                      unsigned& r3, unsigned addr) {
    asm volatile("ldmatrix.sync.aligned.m8n8.x4.shared.b16 {%0,%1,%2,%3}, [%4];"
        : "=r"(r0), "=r"(r1), "=r"(r2), "=r"(r3) : "r"(addr));
}
__device__ __forceinline__ void ldsm4t(unsigned& r0, unsigned& r1, unsigned& r2,
                                       unsigned& r3, unsigned addr) {
    asm volatile("ldmatrix.sync.aligned.m8n8.x4.trans.shared.b16 {%0,%1,%2,%3}, [%4];"
        : "=r"(r0), "=r"(r1), "=r"(r2), "=r"(r3) : "r"(addr));
}
__device__ __forceinline__ unsigned s2u(const void* p) {
    return (unsigned)__cvta_generic_to_shared(p);
}
__device__ __forceinline__ void cp16(unsigned dst, const void* src) {
    asm volatile("cp.async.cg.shared.global [%0], [%1], 16;" :: "r"(dst), "l"(src));
}
#define CPCOMMIT() asm volatile("cp.async.commit_group;")

// GEMM tiling: 128x128 block, K-step 64 (4 x k16), 8 warps (2x4), 3-stage,
// SW128-swizzled staging (128B rows, no pad).
#define SWZ(o)  ((o) ^ (((o) >> 3) & 0x70))
#define GTILE2 16384          // 128 rows x 128 B per operand tile
#define GSTG2  32768          // A + B per stage
#define GSMEM2 (3*GSTG2)      // 98304 B
#define CST    133            // qkv epilogue C stride (floats)

// =====================================================================
// Kernel 0: convert inputs to fp16 (once). 8 floats per thread.
// =====================================================================
#define XQ8 (MROWS*CC/8)     // 786432
#define WQ8 (QKV3*CC/8)      // 221184
#define PQ8 (CC*CC/8)        // 73728
#define PR8 (XQ8+WQ8+PQ8)    // 1081344 = 4224*256

__global__ __launch_bounds__(256) void preround_kernel(
    const float* __restrict__ before, const float* __restrict__ after,
    const float* __restrict__ Wqkv, const float* __restrict__ Wp)
{
    int i = blockIdx.x*256 + threadIdx.x;
    const float* src; __half* dst;
    if (i < XQ8) {
        src = (i < XQ8/2) ? before + (size_t)i*8 : after + (size_t)(i - XQ8/2)*8;
        dst = g_x + (size_t)i*8;
    } else if (i < XQ8 + WQ8) {
        src = Wqkv + (size_t)(i - XQ8)*8;
        dst = g_wq + (size_t)(i - XQ8)*8;
    } else {
        src = Wp + (size_t)(i - XQ8 - WQ8)*8;
        dst = g_wp + (size_t)(i - XQ8 - WQ8)*8;
    }
    float4 v0 = ((const float4*)src)[0];
    float4 v1 = ((const float4*)src)[1];
    uint4 o;
    o.x = pack2(v0.x, v0.y); o.y = pack2(v0.z, v0.w);
    o.z = pack2(v1.x, v1.y); o.w = pack2(v1.z, v1.w);
    *(uint4*)dst = o;
}

// =====================================================================
// Kernel 1: QKV GEMM (fp16, K-step 64, 3-stage, SW128) + fused LN.
// =====================================================================
__global__ __launch_bounds__(256, 2) void qkv_gemm_mma(
    const float* __restrict__ ln_g, const float* __restrict__ ln_b)
{
    extern __shared__ __align__(16) unsigned char sq[];
    __shared__ float s_lng[64], s_lnb[64];
    const int tid = threadIdx.x;
    if (tid < 64) { s_lng[tid] = ln_g[tid]; s_lnb[tid] = ln_b[tid]; }

    const int warp = tid >> 5, lane = tid & 31;
    const int wm = warp >> 2, wn = warp & 3;
    const int g = lane >> 2, t = lane & 3;
    const int mt = blockIdx.y;
    const int bn = blockIdx.x * 128;
    const unsigned smb = s2u(sq);

    // staging: 4 A + 4 B cp16 per thread per stage (128 rows x 8 chunks each)
    const __half* asr[4]; unsigned ad[4];
    const __half* bsr[4]; unsigned bd[4];
    #pragma unroll
    for (int i = 0; i < 4; i++) {
        int id = tid + i*256, r = id >> 3, ch = id & 7;
        unsigned sw = SWZ((unsigned)(r*128 + ch*16));
        asr[i] = g_x + (size_t)(mt*128 + r)*CC + ch*8;
        ad[i]  = smb + sw;
        bsr[i] = g_wq + (size_t)(bn + r)*CC + ch*8;
        bd[i]  = smb + GTILE2 + sw;
    }
    const unsigned aoffl = (lane & 15)*128 + (lane >> 4)*16;
    const unsigned blinl = ((lane & 7) + ((lane >> 4) & 1)*8)*128 + ((lane >> 3) & 1)*16;

    float acc[4][4][4] = {};

    #pragma unroll
    for (int st = 0; st < 2; st++) {
        #pragma unroll
        for (int i = 0; i < 4; i++) {
            cp16(ad[i] + st*GSTG2, asr[i] + st*64);
            cp16(bd[i] + st*GSTG2, bsr[i] + st*64);
        }
        CPCOMMIT();
    }

    unsigned rdo = 0, wro = 2*GSTG2;
    for (int c = 0; c < 12; c++) {
        if (c < 11) { asm volatile("cp.async.wait_group 1;"); }
        else        { asm volatile("cp.async.wait_group 0;"); }
        __syncthreads();
        if (c < 10) {
            #pragma unroll
            for (int i = 0; i < 4; i++) {
                cp16(ad[i] + wro, asr[i] + (c+2)*64);
                cp16(bd[i] + wro, bsr[i] + (c+2)*64);
            }
            CPCOMMIT();
            wro += GSTG2; if (wro == 3*GSTG2) wro = 0;
        }
        const unsigned Ab = smb + rdo;
        const unsigned Bb = Ab + GTILE2;
        rdo += GSTG2; if (rdo == 3*GSTG2) rdo = 0;
        #pragma unroll
        for (int kk = 0; kk < 4; kk++) {
            const unsigned sa = SWZ(aoffl + kk*32);
            const unsigned sb = SWZ(blinl + kk*32);
            unsigned a[4][4], bq[4][2];
            #pragma unroll
            for (int mf = 0; mf < 4; mf++)
                ldsm4(a[mf][0], a[mf][1], a[mf][2], a[mf][3],
                      Ab + sa + (wm*64 + mf*16)*128);
            #pragma unroll
            for (int g2 = 0; g2 < 2; g2++) {
                unsigned r0, r1, r2, r3;
                ldsm4(r0, r1, r2, r3, Bb + sb + (wn*32 + g2*16)*128);
                bq[2*g2][0] = r0; bq[2*g2][1] = r1;
                bq[2*g2+1][0] = r2; bq[2*g2+1][1] = r3;
            }
            #pragma unroll
            for (int mf = 0; mf < 4; mf++)
                #pragma unroll
                for (int nf = 0; nf < 4; nf++)
                    mma16(acc[mf][nf], a[mf], bq[nf]);
        }
    }
    __syncthreads();   // all warps done before Cs aliases staging

    float* Cs = (float*)sq;
    #pragma unroll
    for (int mf = 0; mf < 4; mf++)
        #pragma unroll
        for (int nf = 0; nf < 4; nf++) {
            int row = wm*64 + mf*16 + g, col = wn*32 + nf*8 + 2*t;
            Cs[row*CST + col]       = acc[mf][nf][0];
            Cs[row*CST + col + 1]   = acc[mf][nf][1];
            Cs[(row+8)*CST + col]   = acc[mf][nf][2];
            Cs[(row+8)*CST + col+1] = acc[mf][nf][3];
        }
    __syncthreads();

    {   // LayerNorm over head_dim=64 (2 head-groups per 128-col tile), fp16 out
        int row = tid >> 1, grp = tid & 1;
        const float* src = Cs + row*CST + grp*64;
        float sum = 0.f, sqs = 0.f;
        #pragma unroll
        for (int j = 0; j < 64; j++) { float x = src[j]; sum += x; sqs += x*x; }
        float mu = sum * (1.f/64.f);
        float var = sqs * (1.f/64.f) - mu*mu;
        float rs = rsqrtf(var + 1e-5f);
        int gm = mt*128 + row;
        int s = gm >> 12, b = (gm >> 10) & 3, n = gm & 1023;
        int tq = bn / CC;                       // 0=q,1=k,2=v (tile never straddles)
        int h = ((bn % CC) >> 6) + grp;
        __half* dst = (tq == 0 ? g_q : tq == 1 ? g_k : g_v)
                    + ((((size_t)(s*BB+b)*HH + h)*NN + n)*HD);
        #pragma unroll
        for (int j = 0; j < 64; j += 2) {
            float v0 = (src[j+0]-mu)*rs*s_lng[j+0] + s_lnb[j+0];
            float v1 = (src[j+1]-mu)*rs*s_lng[j+1] + s_lnb[j+1];
            *(__half2*)(dst + j) = __floats2half2_rn(v0, v1);
        }
    }
}

// =====================================================================
// Kernel 2: attention, fp16 m16n8k16. 256 thr = 8 warps, q-tile 128,
// kv-tile 128 (two 64-wide softmax half-updates per tile), 2 CTAs/SM.
// Q hoisted to regs; P packed straight from accumulators; K/V double-
// buffered cp.async. smem: Q 18432 + 2xK 36864 + 2xV 36864 = 92160 B.
// =====================================================================
#define ARS 144               // 64 halves + 8 pad = 144 B per row
#define QB  0
#define KB0 (128*ARS)         // 18432
#define VB0 (KB0 + 2*128*ARS) // 55296
#define ATTN_SMEM (VB0 + 2*128*ARS)   // 92160

__global__ __launch_bounds__(256, 2) void attn_mma() {
    extern __shared__ __align__(16) unsigned char sa[];
    const unsigned smb = s2u(sa);

    const int bx = blockIdx.x;
    const int qt = bx & 7;
    const int h  = (bx >> 3) % 12;
    const int b  = (bx / 96) & 3;
    const int p  = bx / 384;
    const int qs = 1 - p, kvs = p;

    const __half* qptr = g_q + (((size_t)(qs*BB+b)*HH + h)*NN + qt*128)*HD;
    const __half* kptr = g_k + (((size_t)(kvs*BB+b)*HH + h)*NN)*HD;
    const __half* vptr = g_v + (((size_t)(kvs*BB+b)*HH + h)*NN)*HD;

    const int tid = threadIdx.x, w = tid >> 5, lane = tid & 31;
    const int g = lane >> 2, t = lane & 3;

    const unsigned aoffA = ((lane & 15)*ARS + (lane >> 4)*16);
    const unsigned boffK = (((lane & 7) + ((lane >> 4) & 1)*8)*ARS + ((lane >> 3) & 1)*16);
    const unsigned boffV = (((lane & 7) + ((lane >> 3) & 1)*8)*ARS + (lane >> 4)*16);

    // staging coords: 128 rows x 8 chunks for K and V, 4 cp16 each per thread
    int srow[4], sch[4];
    #pragma unroll
    for (int i = 0; i < 4; i++) {
        int id = tid + i*256; srow[i] = id >> 3; sch[i] = id & 7;
    }

    // prefetch kc=0 into buffer 0
    #pragma unroll
    for (int i = 0; i < 4; i++) {
        cp16(smb + KB0 + srow[i]*ARS + sch[i]*16, kptr + srow[i]*64 + sch[i]*8);
        cp16(smb + VB0 + srow[i]*ARS + sch[i]*16, vptr + srow[i]*64 + sch[i]*8);
    }
    CPCOMMIT();

    // stage Q (128x64 fp16) and hoist fragments to registers
    #pragma unroll
    for (int i = 0; i < 4; i++) {
        int id = tid + i*256, row = id >> 3, ch = id & 7;
        *(uint4*)(sa + QB + row*ARS + ch*16) = *(const uint4*)(qptr + row*64 + ch*8);
    }
    __syncthreads();
    unsigned q[4][4];
    #pragma unroll
    for (int kk = 0; kk < 4; kk++)
        ldsm4(q[kk][0], q[kk][1], q[kk][2], q[kk][3],
              smb + QB + (w*16)*ARS + kk*32 + aoffA);

    const float SC = 0.125f * 1.44269504088896f;   // scale * log2(e)
    float o[8][4] = {};
    float m0 = -1e30f, m1 = -1e30f, l0 = 0.f, l1 = 0.f;

    for (int kc = 0; kc < 8; kc++) {
        __syncthreads();                   // readers of buf[(kc+1)&1] done
        if (kc < 7) {
            const __half* kp = kptr + (kc+1)*128*64;
            const __half* vp = vptr + (kc+1)*128*64;
            const unsigned kb = smb + KB0 + ((kc+1)&1)*(128*ARS);
            const unsigned vb = smb + VB0 + ((kc+1)&1)*(128*ARS);
            #pragma unroll
            for (int i = 0; i < 4; i++) {
                cp16(kb + srow[i]*ARS + sch[i]*16, kp + srow[i]*64 + sch[i]*8);
                cp16(vb + srow[i]*ARS + sch[i]*16, vp + srow[i]*64 + sch[i]*8);
            }
            CPCOMMIT();
            asm volatile("cp.async.wait_group 1;");
        } else {
            asm volatile("cp.async.wait_group 0;");
        }
        __syncthreads();                   // buf[kc&1] visible

        const unsigned Kb = smb + KB0 + (kc&1)*(128*ARS);
        const unsigned Vb = smb + VB0 + (kc&1)*(128*ARS);

        #pragma unroll
        for (int half = 0; half < 2; half++) {
            const unsigned Kh = Kb + half*64*ARS;
            const unsigned Vh = Vb + half*64*ARS;

            // S = Q K^T over 64 kv columns
            float s[8][4] = {};
            #pragma unroll
            for (int kk = 0; kk < 4; kk++) {
                #pragma unroll
                for (int j2 = 0; j2 < 4; j2++) {
                    unsigned r0, r1, r2, r3;
                    ldsm4(r0, r1, r2, r3, Kh + (j2*16)*ARS + kk*32 + boffK);
                    unsigned bf0[2] = {r0, r1}, bf1[2] = {r2, r3};
                    mma16(s[2*j2], q[kk], bf0);
                    mma16(s[2*j2+1], q[kk], bf1);
                }
            }

            // online softmax (warp-local; rows g and g+8)
            float mx0 = -1e30f, mx1 = -1e30f;
            #pragma unroll
            for (int nf = 0; nf < 8; nf++) {
                #pragma unroll
                for (int j = 0; j < 4; j++) s[nf][j] *= SC;
                mx0 = fmaxf(mx0, fmaxf(s[nf][0], s[nf][1]));
                mx1 = fmaxf(mx1, fmaxf(s[nf][2], s[nf][3]));
            }
            mx0 = fmaxf(mx0, __shfl_xor_sync(0xffffffffu, mx0, 1));
            mx0 = fmaxf(mx0, __shfl_xor_sync(0xffffffffu, mx0, 2));
            mx1 = fmaxf(mx1, __shfl_xor_sync(0xffffffffu, mx1, 1));
            mx1 = fmaxf(mx1, __shfl_xor_sync(0xffffffffu, mx1, 2));
            float M0 = fmaxf(m0, mx0), M1 = fmaxf(m1, mx1);
            float c0 = ex2f(m0 - M0), c1 = ex2f(m1 - M1);
            float ls0 = 0.f, ls1 = 0.f;
            #pragma unroll
            for (int nf = 0; nf < 8; nf++) {
                s[nf][0] = ex2f(s[nf][0] - M0);
                s[nf][1] = ex2f(s[nf][1] - M0);
                s[nf][2] = ex2f(s[nf][2] - M1);
                s[nf][3] = ex2f(s[nf][3] - M1);
                ls0 += s[nf][0] + s[nf][1];
                ls1 += s[nf][2] + s[nf][3];
            }
            ls0 += __shfl_xor_sync(0xffffffffu, ls0, 1);
            ls0 += __shfl_xor_sync(0xffffffffu, ls0, 2);
            ls1 += __shfl_xor_sync(0xffffffffu, ls1, 1);
            ls1 += __shfl_xor_sync(0xffffffffu, ls1, 2);
            l0 = l0*c0 + ls0; l1 = l1*c1 + ls1;
            m0 = M0; m1 = M1;
            #pragma unroll
            for (int nf = 0; nf < 8; nf++) {
                o[nf][0] *= c0; o[nf][1] *= c0; o[nf][2] *= c1; o[nf][3] *= c1;
            }

            // O += P @ V : P packed from accumulators, V via ldmatrix.trans
            #pragma unroll
            for (int kc2 = 0; kc2 < 4; kc2++) {
                unsigned a[4];
                a[0] = pack2(s[2*kc2][0],   s[2*kc2][1]);
                a[1] = pack2(s[2*kc2][2],   s[2*kc2][3]);
                a[2] = pack2(s[2*kc2+1][0], s[2*kc2+1][1]);
                a[3] = pack2(s[2*kc2+1][2], s[2*kc2+1][3]);
                #pragma unroll
                for (int j = 0; j < 4; j++) {
                    unsigned r0, r1, r2, r3;
                    ldsm4t(r0, r1, r2, r3, Vh + (kc2*16)*ARS + j*32 + boffV);
                    unsigned bf0[2] = {r0, r1}, bf1[2] = {r2, r3};
                    mma16(o[2*j], a, bf0);
                    mma16(o[2*j+1], a, bf1);
                }
            }
        }
    }

    const int qrow = qt*128 + w*16;
    float inv0 = 1.f / l0, inv1 = 1.f / l1;
    __half* op = g_ctx + (((size_t)(p*BB+b)*HH + h)*NN + qrow)*HD;
    #pragma unroll
    for (int nf = 0; nf < 8; nf++) {
        *(__half2*)(op + g*64 + nf*8 + 2*t) =
            __floats2half2_rn(o[nf][0]*inv0, o[nf][1]*inv0);
        *(__half2*)(op + (g+8)*64 + nf*8 + 2*t) =
            __floats2half2_rn(o[nf][2]*inv1, o[nf][3]*inv1);
    }
}

// =====================================================================
// Kernel 3: projection GEMM (fp16, K-step 64 = one head, 3-stage, SW128)
// + bias + q-residual -> f32 out.
// =====================================================================
__global__ __launch_bounds__(256, 2) void proj_gemm_mma(
    const float* __restrict__ bias, float* __restrict__ out)
{
    extern __shared__ __align__(16) unsigned char sp[];
    const int tid = threadIdx.x;
    const int warp = tid >> 5, lane = tid & 31;
    const int wm = warp >> 2, wn = warp & 3;
    const int g = lane >> 2, t = lane & 3;
    const int mt = blockIdx.y;
    const int bn = blockIdx.x * 128;
    const unsigned smb = s2u(sp);

    const __half* actx[4]; unsigned ad[4];
    const __half* bsr[4]; unsigned bd[4];
    #pragma unroll
    for (int i = 0; i < 4; i++) {
        int id = tid + i*256, r = id >> 3, ch = id & 7;
        int gm = mt*128 + r;
        int pp = gm >> 12, b2 = (gm >> 10) & 3, n = gm & 1023;
        unsigned sw = SWZ((unsigned)(r*128 + ch*16));
        actx[i] = g_ctx + (size_t)(pp*BB + b2)*PERSB + (size_t)n*HD + ch*8;
        ad[i]   = smb + sw;
        bsr[i]  = g_wp + (size_t)(bn + r)*CC + ch*8;
        bd[i]   = smb + GTILE2 + sw;
    }
    const unsigned aoffl = (lane & 15)*128 + (lane >> 4)*16;
    const unsigned blinl = ((lane & 7) + ((lane >> 4) & 1)*8)*128 + ((lane >> 3) & 1)*16;

    float acc[4][4][4] = {};

    // K-chunk c = head c (64 elems): A advance = c*NN*HD, B advance = c*64
    #pragma unroll
    for (int st = 0; st < 2; st++) {
        #pragma unroll
        for (int i = 0; i < 4; i++) {
            cp16(ad[i] + st*GSTG2, actx[i] + (size_t)st*(NN*HD));
            cp16(bd[i] + st*GSTG2, bsr[i] + st*64);
        }
        CPCOMMIT();
    }

    unsigned rdo = 0, wro = 2*GSTG2;
    for (int c = 0; c < 12; c++) {
        if (c < 11) { asm volatile("cp.async.wait_group 1;"); }
        else        { asm volatile("cp.async.wait_group 0;"); }
        __syncthreads();
        if (c < 10) {
            #pragma unroll
            for (int i = 0; i < 4; i++) {
                cp16(ad[i] + wro, actx[i] + (size_t)(c+2)*(NN*HD));
                cp16(bd[i] + wro, bsr[i] + (c+2)*64);
            }
            CPCOMMIT();
            wro += GSTG2; if (wro == 3*GSTG2) wro = 0;
        }
        const unsigned Ab = smb + rdo;
        const unsigned Bb = Ab + GTILE2;
        rdo += GSTG2; if (rdo == 3*GSTG2) rdo = 0;
        #pragma unroll
        for (int kk = 0; kk < 4; kk++) {
            const unsigned sa = SWZ(aoffl + kk*32);
            const unsigned sb = SWZ(blinl + kk*32);
            unsigned a[4][4], bq[4][2];
            #pragma unroll
            for (int mf = 0; mf < 4; mf++)
                ldsm4(a[mf][0], a[mf][1], a[mf][2], a[mf][3],
                      Ab + sa + (wm*64 + mf*16)*128);
            #pragma unroll
            for (int g2 = 0; g2 < 2; g2++) {
                unsigned r0, r1, r2, r3;
                ldsm4(r0, r1, r2, r3, Bb + sb + (wn*32 + g2*16)*128);
                bq[2*g2][0] = r0; bq[2*g2][1] = r1;
                bq[2*g2+1][0] = r2; bq[2*g2+1][1] = r3;
            }
            #pragma unroll
            for (int mf = 0; mf < 4; mf++)
                #pragma unroll
                for (int nf = 0; nf < 4; nf++)
                    mma16(acc[mf][nf], a[mf], bq[nf]);
        }
    }

    // epilogue: bias + fp16 flat-q residual -> f32 d_out
    #pragma unroll
    for (int mf = 0; mf < 4; mf++) {
        #pragma unroll
        for (int rr = 0; rr < 2; rr++) {
            int gm = mt*128 + wm*64 + mf*16 + g + rr*8;
            int pp = gm >> 12, b2 = (gm >> 10) & 3, n = gm & 1023;
            const __half* qres = g_q + (size_t)((1-pp)*BB + b2)*PERSB + (size_t)n*CC;
            #pragma unroll
            for (int nf = 0; nf < 4; nf++) {
                int col = bn + wn*32 + nf*8 + 2*t;
                float2 qr = __half22float2(*(const __half2*)(qres + col));
                float2 r;
                r.x = acc[mf][nf][2*rr+0] + __ldg(bias + col)   + qr.x;
                r.y = acc[mf][nf][2*rr+1] + __ldg(bias + col+1) + qr.y;
                *(float2*)(out + (size_t)gm*CC + col) = r;
            }
        }
    }
}

// =====================================================================
extern "C" void kernel_launch(void* const* d_in, const int* in_sizes, int n_in,
                              void* d_out, int out_size) {
    const float* before = (const float*)d_in[0];
    const float* after  = (const float*)d_in[1];
    const float* W_qkv  = (const float*)d_in[2];
    const float* ln_g   = (const float*)d_in[3];
    const float* ln_b   = (const float*)d_in[4];
    const float* W_proj = (const float*)d_in[5];
    const float* b_proj = (const float*)d_in[6];
    float* out = (float*)d_out;

    const int gemm_smem = GSMEM2;             // 98304 (>= Cs 68096)
    const int attn_smem = ATTN_SMEM;          // 92160

    // 0) convert inputs to fp16
    preround_kernel<<<PR8/256, 256>>>(before, after, W_qkv, W_proj);

    // 1) QKV GEMM + fused LN: grid (2304/128, 8192/128)
    {
        cudaFuncSetAttribute(qkv_gemm_mma, cudaFuncAttributeMaxDynamicSharedMemorySize, gemm_smem);
        dim3 grid(QKV3/128, MROWS/128);
        qkv_gemm_mma<<<grid, 256, gemm_smem>>>(ln_g, ln_b);
    }
    // 2) Attention: 768 blocks
    {
        cudaFuncSetAttribute(attn_mma, cudaFuncAttributeMaxDynamicSharedMemorySize, attn_smem);
        attn_mma<<<768, 256, attn_smem>>>();
    }
    // 3) Projection GEMM: grid (768/128, 8192/128)
    {
        cudaFuncSetAttribute(proj_gemm_mma, cudaFuncAttributeMaxDynamicSharedMemorySize, gemm_smem);
        dim3 grid(CC/128, MROWS/128);
        proj_gemm_mma<<<grid, 256, gemm_smem>>>(b_proj, out);
    }
}